// round 15
// baseline (speedup 1.0000x reference)
#include <cuda_runtime.h>
#include <cuda_bf16.h>
#include <math.h>
#include <stdint.h>

#define B_   2
#define S_   512
#define P_   64
#define T_   576
#define D_   1024
#define L_   4
#define DI_  2048
#define DS_  16
#define DR_  64
#define PCD_ 768
#define M_   (B_*T_)   // 1152

// ---------------- static scratch ----------------
__device__ float g_h   [M_*D_];
__device__ float g_dt  [M_*DI_];
__device__ float g_bc  [M_*32];         // [B(16) | C(16)] per row, fp32

// split-K partial buffers (no atomics)
__device__ float g_part16[16*M_*128];   // x_proj partials (ldc padded to 128)
__device__ float g_part4 [4*M_*D_];     // out_proj partials
__device__ float g_pp1   [12*128*D_];   // prepend gemm1 partials
__device__ float g_pp2   [16*128*D_];   // prepend gemm2 partials

__device__ __align__(16) __nv_bfloat16 g_xz_h [M_*2*DI_];
__device__ __align__(16) __nv_bfloat16 g_xn_h [M_*D_];
__device__ __align__(16) __nv_bfloat16 g_xi_h [M_*DI_];
__device__ __align__(16) __nv_bfloat16 g_y_h  [M_*DI_];
__device__ __align__(16) __nv_bfloat16 g_dtr_h[M_*DR_];
__device__ __align__(16) __nv_bfloat16 g_pc_h [128*PCD_];
__device__ __align__(16) __nv_bfloat16 g_p1_h [128*D_];

// weights: bf16
__device__ __align__(16) __nv_bfloat16 g_ipw_h[L_*2*DI_*D_];
__device__ __align__(16) __nv_bfloat16 g_opw_h[L_*D_*DI_];
__device__ __align__(16) __nv_bfloat16 g_xpw_h[L_*128*DI_];   // N padded 96->128
__device__ __align__(16) __nv_bfloat16 g_dtw_h[L_*DI_*DR_];
__device__ __align__(16) __nv_bfloat16 g_w1t  [D_*PCD_];      // w1^T bf16
__device__ __align__(16) __nv_bfloat16 g_w2t  [D_*D_];        // w2^T bf16

// ---------------- helpers ----------------
__device__ __forceinline__ float siluf(float x) { return x / (1.f + __expf(-x)); }
__device__ __forceinline__ float softplusf(float x) {
    return x > 20.f ? x : log1pf(__expf(x));
}
__device__ __forceinline__ uint32_t smem_u32(const void* p) {
    uint32_t a;
    asm("{ .reg .u64 t; cvta.to.shared.u64 t, %1; cvt.u32.u64 %0, t; }" : "=r"(a) : "l"(p));
    return a;
}
__device__ __forceinline__ uint32_t pack2(float a, float b) {
    __nv_bfloat162 t = __floats2bfloat162_rn(a, b);
    return *(uint32_t*)&t;
}
__device__ __forceinline__ void cvt_store4(float4 v, __nv_bfloat16* __restrict__ hp, size_t i4) {
    uint2 o;
    o.x = pack2(v.x, v.y);
    o.y = pack2(v.z, v.w);
    ((uint2*)hp)[i4] = o;
}
__device__ __forceinline__ float bf2f(__nv_bfloat16 v) { return __bfloat162float(v); }
__device__ __forceinline__ float4 f4add(float4 a, float4 b) {
    return make_float4(a.x+b.x, a.y+b.y, a.z+b.z, a.w+b.w);
}

// ---------------- async copy / ldmatrix / mma primitives ----------------
__device__ __forceinline__ void cp16(uint32_t s, const void* g) {
    asm volatile("cp.async.ca.shared.global [%0], [%1], 16;" :: "r"(s), "l"(g));
}
__device__ __forceinline__ void cp_commit() {
    asm volatile("cp.async.commit_group;" ::: "memory");
}
template<int N>
__device__ __forceinline__ void cp_wait() {
    asm volatile("cp.async.wait_group %0;" :: "n"(N) : "memory");
}
#define LDSM4(r0,r1,r2,r3,addr) \
    asm volatile("ldmatrix.sync.aligned.m8n8.x4.shared.b16 {%0,%1,%2,%3}, [%4];" \
        : "=r"(r0),"=r"(r1),"=r"(r2),"=r"(r3) : "r"(addr))

__device__ __forceinline__ void mma16816(float* c, const uint32_t* a, const uint32_t* b) {
    asm volatile(
        "mma.sync.aligned.m16n8k16.row.col.f32.bf16.bf16.f32 "
        "{%0,%1,%2,%3}, {%4,%5,%6,%7}, {%8,%9}, {%0,%1,%2,%3};"
        : "+f"(c[0]), "+f"(c[1]), "+f"(c[2]), "+f"(c[3])
        : "r"(a[0]), "r"(a[1]), "r"(a[2]), "r"(a[3]), "r"(b[0]), "r"(b[1]));
}

__device__ __forceinline__ uint32_t soff(int r, int ch) {
    return (uint32_t)(r * 64 + ((ch ^ ((r >> 1) & 3)) << 4));
}

// ---------------- pipelined bf16 tensor-core GEMM ----------------
// EPI: 0 = store f32, 3 = store bf16, 4 = store f32 partial at + z*zs
#define STAGE_BYTES 16384   // AH 8K | BH 8K
#define NSTAGE 5
#define GEMM_DYN (NSTAGE*STAGE_BYTES + 128)

template<int EPI>
__global__ void __launch_bounds__(256, 2)
tc_gemm(const __nv_bfloat16* __restrict__ Ah,
        const __nv_bfloat16* __restrict__ Bh,
        void* __restrict__ Cv,
        int K, int ldc, size_t zs)
{
    extern __shared__ __align__(16) char dsm[];
    const uint32_t sb = (smem_u32(dsm) + 127u) & ~127u;

    const int tid  = threadIdx.x;
    const int lane = tid & 31;
    const int wid  = tid >> 5;
    const int wm   = wid >> 1;
    const int wn   = wid & 1;
    const int m0   = blockIdx.x * 128;
    const int n0   = blockIdx.y * 128;
    const int kPer = K / gridDim.z;
    const int kBeg = blockIdx.z * kPer;
    const int nIter = kPer >> 5;

    const __nv_bfloat16* gAh = Ah + (size_t)m0 * K + kBeg;
    const __nv_bfloat16* gBh = Bh + (size_t)n0 * K + kBeg;

    const int sr = tid >> 2;
    const int sc = tid & 3;

    auto load_stage = [&](int slot, int kof) {
        const uint32_t st = sb + slot * STAGE_BYTES;
        #pragma unroll
        for (int p = 0; p < 2; p++) {
            int r = sr + p * 64;
            cp16(st + soff(r, sc), gAh + (size_t)r * K + kof + sc * 8);
        }
        #pragma unroll
        for (int p = 0; p < 2; p++) {
            int r = sr + p * 64;
            cp16(st + 8192 + soff(r, sc), gBh + (size_t)r * K + kof + sc * 8);
        }
    };

    float acc[2][8][4];
    #pragma unroll
    for (int mi = 0; mi < 2; mi++)
        #pragma unroll
        for (int ni = 0; ni < 8; ni++)
            #pragma unroll
            for (int q = 0; q < 4; q++) acc[mi][ni][q] = 0.f;

    #pragma unroll
    for (int s = 0; s < NSTAGE - 1; s++) {
        if (s < nIter) load_stage(s, s * 32);
        cp_commit();
    }

    const int g  = lane >> 3;
    const int lr = lane & 7;

    int csl = 0;
    for (int it = 0; it < nIter; it++) {
        cp_wait<NSTAGE - 2>();
        __syncthreads();
        int ns = it + NSTAGE - 1;
        int lsl = csl - 1; if (lsl < 0) lsl += NSTAGE;
        if (ns < nIter) load_stage(lsl, ns * 32);
        cp_commit();

        const uint32_t st = sb + csl * STAGE_BYTES;
        #pragma unroll
        for (int ks = 0; ks < 2; ks++) {
            const int kc8 = ks * 2;
            uint32_t aH[2][4], bH[8][2];
            #pragma unroll
            for (int mi = 0; mi < 2; mi++) {
                int r  = wm * 32 + mi * 16 + (g & 1) * 8 + lr;
                int ch = kc8 + (g >> 1);
                uint32_t ad = st + soff(r, ch);
                LDSM4(aH[mi][0], aH[mi][1], aH[mi][2], aH[mi][3], ad);
            }
            #pragma unroll
            for (int t = 0; t < 4; t++) {
                int r  = wn * 64 + t * 16 + (g >> 1) * 8 + lr;
                int ch = kc8 + (g & 1);
                uint32_t ad = st + 8192 + soff(r, ch);
                LDSM4(bH[2*t][0], bH[2*t][1], bH[2*t+1][0], bH[2*t+1][1], ad);
            }
            #pragma unroll
            for (int mi = 0; mi < 2; mi++)
                #pragma unroll
                for (int ni = 0; ni < 8; ni++) mma16816(acc[mi][ni], aH[mi], bH[ni]);
        }
        csl++; if (csl == NSTAGE) csl = 0;
    }

    float* Cf = (EPI == 4) ? (float*)Cv + zs * blockIdx.z : (float*)Cv;

    #pragma unroll
    for (int mi = 0; mi < 2; mi++) {
        #pragma unroll
        for (int ni = 0; ni < 8; ni++) {
            int r  = m0 + wm * 32 + mi * 16 + (lane >> 2);
            int cc = n0 + wn * 64 + ni * 8 + (lane & 3) * 2;
            #pragma unroll
            for (int half = 0; half < 2; half++) {
                int rr = r + half * 8;
                float v0 = acc[mi][ni][half * 2];
                float v1 = acc[mi][ni][half * 2 + 1];
                size_t o = (size_t)rr * ldc + cc;
                if (EPI == 3) {
                    ((uint32_t*)Cv)[o >> 1] = pack2(v0, v1);
                } else {
                    *(float2*)(Cf + o) = make_float2(v0, v1);
                }
            }
        }
    }
}

// ---------------- dt_proj: softplus(dtr(bf16) @ W(bf16)^T + b), K=64 ----------------
__global__ void __launch_bounds__(256, 2)
dtproj_kernel(const __nv_bfloat16* __restrict__ dtr,
              const __nv_bfloat16* __restrict__ W,
              const float* __restrict__ bias,
              float* __restrict__ C)
{
    __shared__ __align__(16) char sm[32768];
    const uint32_t sb = smem_u32(sm);

    const int tid  = threadIdx.x;
    const int lane = tid & 31;
    const int wid  = tid >> 5;
    const int wm   = wid >> 1;
    const int wn   = wid & 1;
    const int m0   = blockIdx.x * 128;
    const int n0   = blockIdx.y * 128;

    {
        int r = tid >> 2, ch = tid & 3;
        #pragma unroll
        for (int p = 0; p < 2; p++) {
            int rr = r + p * 64;
            #pragma unroll
            for (int s = 0; s < 2; s++) {
                cp16(sb + s * 8192 + soff(rr, ch),
                     dtr + (size_t)(m0 + rr) * 64 + s * 32 + ch * 8);
                cp16(sb + 16384 + s * 8192 + soff(rr, ch),
                     W + (size_t)(n0 + rr) * 64 + s * 32 + ch * 8);
            }
        }
        cp_commit();
    }
    cp_wait<0>();
    __syncthreads();

    float acc[2][8][4];
    #pragma unroll
    for (int mi = 0; mi < 2; mi++)
        #pragma unroll
        for (int ni = 0; ni < 8; ni++)
            #pragma unroll
            for (int q = 0; q < 4; q++) acc[mi][ni][q] = 0.f;

    const int g  = lane >> 3;
    const int lr = lane & 7;

    #pragma unroll
    for (int ks = 0; ks < 4; ks++) {
        const int sub = ks >> 1;
        const int kc8 = (ks & 1) * 2;
        const uint32_t stA = sb + sub * 8192;
        const uint32_t stB = sb + 16384 + sub * 8192;
        uint32_t aH[2][4], bH[8][2];
        #pragma unroll
        for (int mi = 0; mi < 2; mi++) {
            int r  = wm * 32 + mi * 16 + (g & 1) * 8 + lr;
            int ch = kc8 + (g >> 1);
            LDSM4(aH[mi][0], aH[mi][1], aH[mi][2], aH[mi][3], stA + soff(r, ch));
        }
        #pragma unroll
        for (int t = 0; t < 4; t++) {
            int r  = wn * 64 + t * 16 + (g >> 1) * 8 + lr;
            int ch = kc8 + (g & 1);
            LDSM4(bH[2*t][0], bH[2*t][1], bH[2*t+1][0], bH[2*t+1][1], stB + soff(r, ch));
        }
        #pragma unroll
        for (int mi = 0; mi < 2; mi++)
            #pragma unroll
            for (int ni = 0; ni < 8; ni++) mma16816(acc[mi][ni], aH[mi], bH[ni]);
    }

    #pragma unroll
    for (int mi = 0; mi < 2; mi++) {
        #pragma unroll
        for (int ni = 0; ni < 8; ni++) {
            int r  = m0 + wm * 32 + mi * 16 + (lane >> 2);
            int cc = n0 + wn * 64 + ni * 8 + (lane & 3) * 2;
            #pragma unroll
            for (int half = 0; half < 2; half++) {
                int rr = r + half * 8;
                float v0 = softplusf(acc[mi][ni][half * 2]     + bias[cc]);
                float v1 = softplusf(acc[mi][ni][half * 2 + 1] + bias[cc + 1]);
                *(float2*)(C + (size_t)rr * DI_ + cc) = make_float2(v0, v1);
            }
        }
    }
}

// ---------------- merged convert + transpose kernel ----------------
#define CW_N1 (L_*2*DI_*D_/4)
#define CW_N2 (L_*D_*DI_/4)
#define CW_N3 (L_*DI_*DR_/4)
#define CW_N4 (L_*128*(DI_/4))
#define CW_N5 (128*PCD_/4)
#define CW_TOT (CW_N1+CW_N2+CW_N3+CW_N4+CW_N5)
#define CW_BLK ((CW_TOT+255)/256)
#define TP_W1  ((D_/32)*(PCD_/32))
#define TP_W2  ((D_/32)*(D_/32))

__global__ void convert_all(const float* __restrict__ ipw, __nv_bfloat16* __restrict__ ipwh,
                            const float* __restrict__ opw, __nv_bfloat16* __restrict__ opwh,
                            const float* __restrict__ dtw, __nv_bfloat16* __restrict__ dtwh,
                            const float* __restrict__ xpw, __nv_bfloat16* __restrict__ xpwh,
                            const float* __restrict__ pc,  __nv_bfloat16* __restrict__ pch,
                            const float* __restrict__ w1, __nv_bfloat16* __restrict__ w1t,
                            const float* __restrict__ w2, __nv_bfloat16* __restrict__ w2t) {
    if (blockIdx.x >= CW_BLK) {
        __shared__ float tile[32][33];
        int tb = blockIdx.x - CW_BLK;
        const float* in;
        __nv_bfloat16* out;
        int K, bx, by;
        if (tb < TP_W1) { in = w1; out = w1t; K = PCD_; bx = (tb & 31) * 32; by = (tb >> 5) * 32; }
        else { tb -= TP_W1; in = w2; out = w2t; K = D_; bx = (tb & 31) * 32; by = (tb >> 5) * 32; }
        int tx = threadIdx.x & 31, ty = threadIdx.x >> 5;
        #pragma unroll
        for (int i = 0; i < 32; i += 8)
            tile[ty + i][tx] = in[(size_t)(by + ty + i) * D_ + bx + tx];
        __syncthreads();
        #pragma unroll
        for (int i = 0; i < 32; i += 8)
            out[(size_t)(bx + ty + i) * K + by + tx] = __float2bfloat16(tile[tx][ty + i]);
        return;
    }
    int i = blockIdx.x * 256 + threadIdx.x;
    if (i < CW_N1) {
        cvt_store4(((const float4*)ipw)[i], ipwh, i);
    } else if (i < CW_N1 + CW_N2) {
        int j = i - CW_N1;
        cvt_store4(((const float4*)opw)[j], opwh, j);
    } else if (i < CW_N1 + CW_N2 + CW_N3) {
        int j = i - (CW_N1 + CW_N2);
        cvt_store4(((const float4*)dtw)[j], dtwh, j);
    } else if (i < CW_N1 + CW_N2 + CW_N3 + CW_N4) {
        int j = i - (CW_N1 + CW_N2 + CW_N3);
        int k4   = j % (DI_/4);
        int nrow = (j / (DI_/4)) % 128;
        int lay  = j / (128 * (DI_/4));
        float4 v = make_float4(0.f, 0.f, 0.f, 0.f);
        if (nrow < 96)
            v = ((const float4*)xpw)[(size_t)(lay * 96 + nrow) * (DI_/4) + k4];
        cvt_store4(v, xpwh, j);
    } else if (i < CW_TOT) {
        int j = i - (CW_N1 + CW_N2 + CW_N3 + CW_N4);
        cvt_store4(((const float4*)pc)[j], pch, j);
    }
}

// reduce 12 prepend-gemm1 partials + silu + cvt -> bf16
__global__ void silu_cvt_red(const float* __restrict__ parts, __nv_bfloat16* __restrict__ out) {
    int i = blockIdx.x * 256 + threadIdx.x;
    if (i >= 128*D_/4) return;
    float4 v = make_float4(0.f,0.f,0.f,0.f);
    #pragma unroll
    for (int z = 0; z < 12; z++)
        v = f4add(v, ((const float4*)parts)[(size_t)z*(128*D_/4) + i]);
    v = make_float4(siluf(v.x), siluf(v.y), siluf(v.z), siluf(v.w));
    cvt_store4(v, out, i);
}

// reduce 16 x_proj partials -> dtr bf16 [M,64] + bc fp32 [M,32]
__global__ void reduce_xdbl(const float* __restrict__ parts,
                            __nv_bfloat16* __restrict__ dtr,
                            float* __restrict__ bc) {
    int i = blockIdx.x * 256 + threadIdx.x;
    if (i >= M_ * 24) return;
    int m = i / 24, c4 = i % 24;
    float4 acc = make_float4(0.f,0.f,0.f,0.f);
    #pragma unroll
    for (int z = 0; z < 16; z++)
        acc = f4add(acc, ((const float4*)parts)[(size_t)z*(M_*128/4) + (size_t)m*32 + c4]);
    if (c4 < 16) cvt_store4(acc, dtr, (size_t)m*16 + c4);
    else         ((float4*)bc)[(size_t)m*8 + (c4 - 16)] = acc;
}

// ---------------- fused build_h (16-way partial reduce) + rmsnorm (layer 0) ----------------
__global__ void build_rms_kernel(const float* __restrict__ pp2,
                                 const float* __restrict__ x,
                                 const float* __restrict__ w,
                                 float* __restrict__ h,
                                 __nv_bfloat16* __restrict__ oh) {
    int row = blockIdx.x;
    int b = row / T_;
    int t = row % T_;
    int tid = threadIdx.x;
    float4 x4;
    if (t < P_) {
        x4 = make_float4(0.f,0.f,0.f,0.f);
        size_t o = (size_t)(b*P_ + t)*(D_/4) + tid;
        #pragma unroll
        for (int z = 0; z < 16; z++)
            x4 = f4add(x4, ((const float4*)pp2)[(size_t)z*(128*D_/4) + o]);
    } else {
        x4 = ((const float4*)(x + (size_t)(b*S_ + (t - P_))*D_))[tid];
    }
    ((float4*)(h + (size_t)row*D_))[tid] = x4;
    float s = x4.x*x4.x + x4.y*x4.y + x4.z*x4.z + x4.w*x4.w;
    #pragma unroll
    for (int o = 16; o; o >>= 1) s += __shfl_xor_sync(0xffffffffu, s, o);
    __shared__ float ws[8];
    __shared__ float scale_s;
    if ((tid & 31) == 0) ws[tid >> 5] = s;
    __syncthreads();
    if (tid == 0) {
        float tt = 0.f;
        #pragma unroll
        for (int i = 0; i < 8; i++) tt += ws[i];
        scale_s = rsqrtf(tt / (float)D_ + 1e-5f);
    }
    __syncthreads();
    float sc = scale_s;
    float4 wv = ((const float4*)w)[tid];
    float4 v = make_float4(x4.x*sc*wv.x, x4.y*sc*wv.y, x4.z*sc*wv.z, x4.w*sc*wv.w);
    cvt_store4(v, oh, (size_t)row*(D_/4) + tid);
}

// rmsnorm with fused out_proj 4-partial accumulate; writes back h
__global__ void rmsnorm_acc_kernel(float* __restrict__ h,
                                   const float* __restrict__ parts,
                                   const float* __restrict__ w,
                                   __nv_bfloat16* __restrict__ oh) {
    int row = blockIdx.x;
    int tid = threadIdx.x;
    size_t o = (size_t)row*(D_/4) + tid;
    float4 x4 = ((const float4*)h)[o];
    #pragma unroll
    for (int z = 0; z < 4; z++)
        x4 = f4add(x4, ((const float4*)parts)[(size_t)z*(M_*D_/4) + o]);
    ((float4*)h)[o] = x4;
    float s = x4.x*x4.x + x4.y*x4.y + x4.z*x4.z + x4.w*x4.w;
    #pragma unroll
    for (int q = 16; q; q >>= 1) s += __shfl_xor_sync(0xffffffffu, s, q);
    __shared__ float ws[8];
    __shared__ float scale_s;
    if ((tid & 31) == 0) ws[tid >> 5] = s;
    __syncthreads();
    if (tid == 0) {
        float t = 0.f;
        #pragma unroll
        for (int i = 0; i < 8; i++) t += ws[i];
        scale_s = rsqrtf(t / (float)D_ + 1e-5f);
    }
    __syncthreads();
    float sc = scale_s;
    float4 wv = ((const float4*)w)[tid];
    float4 v = make_float4(x4.x*sc*wv.x, x4.y*sc*wv.y, x4.z*sc*wv.z, x4.w*sc*wv.w);
    cvt_store4(v, oh, o);
}

// final rmsnorm with fused out_proj 4-partial accumulate
__global__ void final_acc_kernel(const float* __restrict__ h,
                                 const float* __restrict__ parts,
                                 const float* __restrict__ w,
                                 float* __restrict__ out) {
    int row = blockIdx.x;
    int b = row >> 9;
    int t = row & 511;
    int hrow = b*T_ + P_ + t;
    int tid = threadIdx.x;
    size_t o = (size_t)hrow*(D_/4) + tid;
    float4 x4 = ((const float4*)h)[o];
    #pragma unroll
    for (int z = 0; z < 4; z++)
        x4 = f4add(x4, ((const float4*)parts)[(size_t)z*(M_*D_/4) + o]);
    float s = x4.x*x4.x + x4.y*x4.y + x4.z*x4.z + x4.w*x4.w;
    #pragma unroll
    for (int q = 16; q; q >>= 1) s += __shfl_xor_sync(0xffffffffu, s, q);
    __shared__ float ws[8];
    __shared__ float scale_s;
    if ((tid & 31) == 0) ws[tid >> 5] = s;
    __syncthreads();
    if (tid == 0) {
        float tt = 0.f;
        #pragma unroll
        for (int i = 0; i < 8; i++) tt += ws[i];
        scale_s = rsqrtf(tt / (float)D_ + 1e-5f);
    }
    __syncthreads();
    float sc = scale_s;
    float4 wv = ((const float4*)w)[tid];
    float4 o4 = make_float4(x4.x*sc*wv.x, x4.y*sc*wv.y, x4.z*sc*wv.z, x4.w*sc*wv.w);
    ((float4*)(out + (size_t)row*D_))[tid] = o4;
}

// depthwise causal conv (DC=4) + silu; 8 channels/thread, uint4 loads/stores
__global__ void conv_silu8(const __nv_bfloat16* __restrict__ xzh,
                           const float* __restrict__ cw,
                           const float* __restrict__ cb,
                           __nv_bfloat16* __restrict__ xih) {
    int idx = blockIdx.x * blockDim.x + threadIdx.x;
    if (idx >= M_*(DI_/8)) return;

    int e8 = idx % (DI_/8);
    int m  = idx / (DI_/8);
    int t  = m % T_;

    float4 w[8];
    #pragma unroll
    for (int c = 0; c < 8; c++) w[c] = ((const float4*)cw)[e8*8 + c];
    float acc[8];
    {
        float4 b0 = ((const float4*)cb)[e8*2];
        float4 b1 = ((const float4*)cb)[e8*2+1];
        acc[0]=b0.x; acc[1]=b0.y; acc[2]=b0.z; acc[3]=b0.w;
        acc[4]=b1.x; acc[5]=b1.y; acc[6]=b1.z; acc[7]=b1.w;
    }
    #pragma unroll
    for (int j = 0; j < 4; j++) {
        int tt = t - 3 + j;
        if (tt >= 0) {
            uint4 raw = *(const uint4*)(xzh + (size_t)(m - 3 + j)*(2*DI_) + e8*8);
            const __nv_bfloat162* p = (const __nv_bfloat162*)&raw;
            #pragma unroll
            for (int q = 0; q < 4; q++) {
                acc[q*2]   = fmaf(bf2f(p[q].x), ((const float*)&w[q*2])[j],   acc[q*2]);
                acc[q*2+1] = fmaf(bf2f(p[q].y), ((const float*)&w[q*2+1])[j], acc[q*2+1]);
            }
        }
    }
    uint4 o;
    o.x = pack2(siluf(acc[0]), siluf(acc[1]));
    o.y = pack2(siluf(acc[2]), siluf(acc[3]));
    o.z = pack2(siluf(acc[4]), siluf(acc[5]));
    o.w = pack2(siluf(acc[6]), siluf(acc[7]));
    ((uint4*)xih)[idx] = o;
}

// ---------------- selective scan, 512 threads / 32 channels (1 wave) ----------------
// warp w (0..15) computes channels 2w, 2w+1; double-buffered cp.async staging.
__global__ void __launch_bounds__(512)
scan_kernel(const __nv_bfloat16* __restrict__ xzh,
            const __nv_bfloat16* __restrict__ xih,
            const float* __restrict__ bc,
            const float* __restrict__ dt,
            const float* __restrict__ A_log,
            const float* __restrict__ Dp,
            __nv_bfloat16* __restrict__ yh) {
    __shared__ __align__(16) float sdt[2][16][32], sB[2][16][16], sC[2][16][16];
    __shared__ __align__(16) __nv_bfloat16 sxi[2][16][32], sz[2][16][32];
    __shared__ uint32_t sy[16][16];

    const int tid  = threadIdx.x;
    const int lane = tid & 31;
    const int warp = tid >> 5;               // 0..15
    const int blk  = blockIdx.x;             // 0..127
    const int b    = blk >> 6;
    const int e0   = (blk & 63) * 32;
    const int m0   = b * T_;

    const int cloc = 2 * warp + (lane >> 4); // 0..31
    const int s    = lane & 15;
    const int e    = e0 + cloc;

    const float A  = -expf(A_log[(size_t)e*DS_ + s]);
    const float Dv = Dp[e];
    float h = 0.f;

    auto load_chunk = [&](int buf, int tb) {
        if (tid < 128) {                       // dt: 16 rows x 128B
            int r = tid >> 3, c = tid & 7;
            cp16(smem_u32(&sdt[buf][r][c*4]), dt + (size_t)(m0 + tb + r)*DI_ + e0 + c*4);
        } else if (tid < 192) {                // B: 16 rows x 64B
            int t2 = tid - 128;
            int r = t2 >> 2, c = t2 & 3;
            cp16(smem_u32(&sB[buf][r][c*4]), bc + (size_t)(m0 + tb + r)*32 + c*4);
        } else if (tid < 256) {                // C
            int t2 = tid - 192;
            int r = t2 >> 2, c = t2 & 3;
            cp16(smem_u32(&sC[buf][r][c*4]), bc + (size_t)(m0 + tb + r)*32 + 16 + c*4);
        } else if (tid < 320) {                // xi: 16 rows x 64B (32 bf16)
            int t2 = tid - 256;
            int r = t2 >> 2, c = t2 & 3;
            cp16(smem_u32(&sxi[buf][r][c*8]), xih + (size_t)(m0 + tb + r)*DI_ + e0 + c*8);
        } else if (tid < 384) {                // z
            int t2 = tid - 320;
            int r = t2 >> 2, c = t2 & 3;
            cp16(smem_u32(&sz[buf][r][c*8]), xzh + (size_t)(m0 + tb + r)*(2*DI_) + DI_ + e0 + c*8);
        }
    };

    load_chunk(0, 0);
    cp_commit();

    for (int ci = 0; ci < T_/16; ci++) {
        if (ci + 1 < T_/16) load_chunk((ci + 1) & 1, (ci + 1) * 16);
        cp_commit();
        cp_wait<1>();
        __syncthreads();

        const int buf = ci & 1;
        float p[16];
        #pragma unroll
        for (int j = 0; j < 16; j++) {
            float dtv = sdt[buf][j][cloc];
            float dA  = __expf(dtv * A);
            h = fmaf(dA, h, dtv * sB[buf][j][s] * bf2f(sxi[buf][j][cloc]));
            p[j] = h * sC[buf][j][s];
        }
        #pragma unroll
        for (int o = 8; o >= 1; o >>= 1)
            #pragma unroll
            for (int j = 0; j < 16; j++)
                p[j] += __shfl_xor_sync(0xffffffffu, p[j], o);
        #pragma unroll
        for (int j = 0; j < 16; j++) {
            float val = (p[j] + bf2f(sxi[buf][j][cloc]) * Dv) * siluf(bf2f(sz[buf][j][cloc]));
            float v1  = __shfl_down_sync(0xffffffffu, val, 16);
            if (lane == 0) sy[j][warp] = pack2(val, v1);
        }
        __syncthreads();

        if (tid < 256) {
            int t = tid >> 4, q = tid & 15;
            ((uint32_t*)yh)[((size_t)(m0 + ci*16 + t)*DI_ + e0) / 2 + q] = sy[t][q];
        }
        __syncthreads();
    }
}

// ---------------- host orchestration ----------------
extern "C" void kernel_launch(void* const* d_in, const int* in_sizes, int n_in,
                              void* d_out, int out_size) {
    (void)in_sizes; (void)n_in; (void)out_size;
    const float* x      = (const float*)d_in[0];
    const float* pc     = (const float*)d_in[1];
    const float* w1     = (const float*)d_in[2];
    const float* w2     = (const float*)d_in[3];
    const float* norm_w = (const float*)d_in[4];
    const float* ipw    = (const float*)d_in[5];
    const float* cw     = (const float*)d_in[6];
    const float* cb     = (const float*)d_in[7];
    const float* xpw    = (const float*)d_in[8];
    const float* dtw    = (const float*)d_in[9];
    const float* dtb    = (const float*)d_in[10];
    const float* A_log  = (const float*)d_in[11];
    const float* Dparam = (const float*)d_in[12];
    const float* opw    = (const float*)d_in[13];
    const float* fnw    = (const float*)d_in[14];

    float *h, *dtp, *bcp, *part16, *part4, *pp1, *pp2;
    cudaGetSymbolAddress((void**)&h,      g_h);
    cudaGetSymbolAddress((void**)&dtp,    g_dt);
    cudaGetSymbolAddress((void**)&bcp,    g_bc);
    cudaGetSymbolAddress((void**)&part16, g_part16);
    cudaGetSymbolAddress((void**)&part4,  g_part4);
    cudaGetSymbolAddress((void**)&pp1,    g_pp1);
    cudaGetSymbolAddress((void**)&pp2,    g_pp2);

    __nv_bfloat16 *xzh, *xnh, *xih, *yh, *dtrh, *ipwh, *opwh, *xpwh, *dtwh, *pch, *p1h, *w1t, *w2t;
    cudaGetSymbolAddress((void**)&xzh,  g_xz_h);
    cudaGetSymbolAddress((void**)&xnh,  g_xn_h);
    cudaGetSymbolAddress((void**)&xih,  g_xi_h);
    cudaGetSymbolAddress((void**)&yh,   g_y_h);
    cudaGetSymbolAddress((void**)&dtrh, g_dtr_h);
    cudaGetSymbolAddress((void**)&ipwh, g_ipw_h);
    cudaGetSymbolAddress((void**)&opwh, g_opw_h);
    cudaGetSymbolAddress((void**)&xpwh, g_xpw_h);
    cudaGetSymbolAddress((void**)&dtwh, g_dtw_h);
    cudaGetSymbolAddress((void**)&pch,  g_pc_h);
    cudaGetSymbolAddress((void**)&p1h,  g_p1_h);
    cudaGetSymbolAddress((void**)&w1t,  g_w1t);
    cudaGetSymbolAddress((void**)&w2t,  g_w2t);

    cudaFuncSetAttribute(tc_gemm<3>, cudaFuncAttributeMaxDynamicSharedMemorySize, GEMM_DYN);
    cudaFuncSetAttribute(tc_gemm<4>, cudaFuncAttributeMaxDynamicSharedMemorySize, GEMM_DYN);

    // ---- converts + transposes (1 launch) ----
    convert_all<<<CW_BLK + TP_W1 + TP_W2, 256>>>(ipw, ipwh, opw, opwh, dtw, dtwh,
                                                 xpw, xpwh, pc, pch, w1, w1t, w2, w2t);

    // ---- prepend MLP, split-K partials (no atomics) ----
    tc_gemm<4><<<dim3(1, 8, 12), 256, GEMM_DYN>>>(pch, w1t, pp1, PCD_, D_, (size_t)128*D_);
    silu_cvt_red<<<(128*D_/4+255)/256, 256>>>(pp1, p1h);
    tc_gemm<4><<<dim3(1, 8, 16), 256, GEMM_DYN>>>(p1h, w2t, pp2, D_, D_, (size_t)128*D_);
    build_rms_kernel<<<M_, 256>>>(pp2, x, norm_w, h, xnh);

    // ---- 4 mamba layers ----
    for (int l = 0; l < L_; l++) {
        // xz = xn @ in_proj_w^T -> bf16  (288 CTAs)
        tc_gemm<3><<<dim3(9, 32, 1), 256, GEMM_DYN>>>(
            xnh, ipwh + (size_t)l*2*DI_*D_, xzh, D_, 2*DI_, 0);

        conv_silu8<<<(M_*(DI_/8)+255)/256, 256>>>(
            xzh, cw + (size_t)l*DI_*4, cb + (size_t)l*DI_, xih);

        // x_proj partials (144 CTAs, split-K=16)
        tc_gemm<4><<<dim3(9, 1, 16), 256, GEMM_DYN>>>(
            xih, xpwh + (size_t)l*128*DI_, part16, DI_, 128, (size_t)M_*128);
        reduce_xdbl<<<(M_*24+255)/256, 256>>>(part16, dtrh, bcp);

        // dt = softplus(dtr @ dt_proj_w^T + b)
        dtproj_kernel<<<dim3(9, 16), 256>>>(
            dtrh, dtwh + (size_t)l*DI_*DR_, dtb + (size_t)l*DI_, dtp);

        // selective scan + gate -> y bf16 (128 CTAs, single wave)
        scan_kernel<<<B_*(DI_/32), 512>>>(
            xzh, xih, bcp, dtp,
            A_log + (size_t)l*DI_*DS_, Dparam + (size_t)l*DI_, yh);

        // out_proj partials (288 CTAs, split-K=4)
        tc_gemm<4><<<dim3(9, 8, 4), 256, GEMM_DYN>>>(
            yh, opwh + (size_t)l*D_*DI_, part4, DI_, D_, (size_t)M_*D_);

        if (l < L_ - 1)
            rmsnorm_acc_kernel<<<M_, 256>>>(h, part4, norm_w + (size_t)(l+1)*D_, xnh);
        else
            final_acc_kernel<<<B_*S_, 256>>>(h, part4, fnw, (float*)d_out);
    }
}

// round 16
// speedup vs baseline: 1.0848x; 1.0848x over previous
#include <cuda_runtime.h>
#include <cuda_bf16.h>
#include <math.h>
#include <stdint.h>

#define B_   2
#define S_   512
#define P_   64
#define T_   576
#define D_   1024
#define L_   4
#define DI_  2048
#define DS_  16
#define DR_  64
#define PCD_ 768
#define M_   (B_*T_)   // 1152

// ---------------- static scratch ----------------
__device__ float g_h   [M_*D_];
__device__ float g_dt  [M_*DI_];
__device__ float g_bc  [M_*32];         // [B(16) | C(16)] per row, fp32

// split-K partial buffers (no atomics)
__device__ float g_part16[16*M_*128];   // x_proj partials (ldc padded to 128)
__device__ float g_part2 [2*M_*D_];     // out_proj partials
__device__ float g_pp1   [6*128*D_];    // prepend gemm1 partials
__device__ float g_pp2   [8*128*D_];    // prepend gemm2 partials

__device__ __align__(16) __nv_bfloat16 g_xz_h [M_*2*DI_];
__device__ __align__(16) __nv_bfloat16 g_xn_h [M_*D_];
__device__ __align__(16) __nv_bfloat16 g_xi_h [M_*DI_];
__device__ __align__(16) __nv_bfloat16 g_y_h  [M_*DI_];
__device__ __align__(16) __nv_bfloat16 g_dtr_h[M_*DR_];
__device__ __align__(16) __nv_bfloat16 g_pc_h [128*PCD_];
__device__ __align__(16) __nv_bfloat16 g_p1_h [128*D_];

// weights: bf16
__device__ __align__(16) __nv_bfloat16 g_ipw_h[L_*2*DI_*D_];
__device__ __align__(16) __nv_bfloat16 g_opw_h[L_*D_*DI_];
__device__ __align__(16) __nv_bfloat16 g_xpw_h[L_*128*DI_];   // N padded 96->128
__device__ __align__(16) __nv_bfloat16 g_dtw_h[L_*DI_*DR_];
__device__ __align__(16) __nv_bfloat16 g_w1t  [D_*PCD_];      // w1^T bf16
__device__ __align__(16) __nv_bfloat16 g_w2t  [D_*D_];        // w2^T bf16

// ---------------- helpers ----------------
__device__ __forceinline__ float siluf(float x) { return x / (1.f + __expf(-x)); }
__device__ __forceinline__ float softplusf(float x) {
    return x > 20.f ? x : log1pf(__expf(x));
}
__device__ __forceinline__ uint32_t smem_u32(const void* p) {
    uint32_t a;
    asm("{ .reg .u64 t; cvta.to.shared.u64 t, %1; cvt.u32.u64 %0, t; }" : "=r"(a) : "l"(p));
    return a;
}
__device__ __forceinline__ uint32_t pack2(float a, float b) {
    __nv_bfloat162 t = __floats2bfloat162_rn(a, b);
    return *(uint32_t*)&t;
}
__device__ __forceinline__ void cvt_store4(float4 v, __nv_bfloat16* __restrict__ hp, size_t i4) {
    uint2 o;
    o.x = pack2(v.x, v.y);
    o.y = pack2(v.z, v.w);
    ((uint2*)hp)[i4] = o;
}
__device__ __forceinline__ float bf2f(__nv_bfloat16 v) { return __bfloat162float(v); }
__device__ __forceinline__ float4 f4add(float4 a, float4 b) {
    return make_float4(a.x+b.x, a.y+b.y, a.z+b.z, a.w+b.w);
}

// ---------------- async copy / ldmatrix / mma primitives ----------------
__device__ __forceinline__ void cp16(uint32_t s, const void* g) {
    asm volatile("cp.async.ca.shared.global [%0], [%1], 16;" :: "r"(s), "l"(g));
}
__device__ __forceinline__ void cp_commit() {
    asm volatile("cp.async.commit_group;" ::: "memory");
}
template<int N>
__device__ __forceinline__ void cp_wait() {
    asm volatile("cp.async.wait_group %0;" :: "n"(N) : "memory");
}
#define LDSM4(r0,r1,r2,r3,addr) \
    asm volatile("ldmatrix.sync.aligned.m8n8.x4.shared.b16 {%0,%1,%2,%3}, [%4];" \
        : "=r"(r0),"=r"(r1),"=r"(r2),"=r"(r3) : "r"(addr))

__device__ __forceinline__ void mma16816(float* c, const uint32_t* a, const uint32_t* b) {
    asm volatile(
        "mma.sync.aligned.m16n8k16.row.col.f32.bf16.bf16.f32 "
        "{%0,%1,%2,%3}, {%4,%5,%6,%7}, {%8,%9}, {%0,%1,%2,%3};"
        : "+f"(c[0]), "+f"(c[1]), "+f"(c[2]), "+f"(c[3])
        : "r"(a[0]), "r"(a[1]), "r"(a[2]), "r"(a[3]), "r"(b[0]), "r"(b[1]));
}

__device__ __forceinline__ uint32_t soff(int r, int ch) {
    return (uint32_t)(r * 64 + ((ch ^ ((r >> 1) & 3)) << 4));
}

// ---------------- pipelined bf16 tensor-core GEMM ----------------
// EPI: 0 = store f32, 3 = store bf16, 4 = store f32 partial at + z*zs
#define STAGE_BYTES 16384   // AH 8K | BH 8K
#define NSTAGE 6
#define GEMM_DYN (NSTAGE*STAGE_BYTES + 128)

template<int EPI>
__global__ void __launch_bounds__(256, 2)
tc_gemm(const __nv_bfloat16* __restrict__ Ah,
        const __nv_bfloat16* __restrict__ Bh,
        void* __restrict__ Cv,
        int K, int ldc, size_t zs)
{
    extern __shared__ __align__(16) char dsm[];
    const uint32_t sb = (smem_u32(dsm) + 127u) & ~127u;

    const int tid  = threadIdx.x;
    const int lane = tid & 31;
    const int wid  = tid >> 5;
    const int wm   = wid >> 1;
    const int wn   = wid & 1;
    const int m0   = blockIdx.x * 128;
    const int n0   = blockIdx.y * 128;
    const int kPer = K / gridDim.z;
    const int kBeg = blockIdx.z * kPer;
    const int nIter = kPer >> 5;

    const __nv_bfloat16* gAh = Ah + (size_t)m0 * K + kBeg;
    const __nv_bfloat16* gBh = Bh + (size_t)n0 * K + kBeg;

    const int sr = tid >> 2;
    const int sc = tid & 3;

    auto load_stage = [&](int slot, int kof) {
        const uint32_t st = sb + slot * STAGE_BYTES;
        #pragma unroll
        for (int p = 0; p < 2; p++) {
            int r = sr + p * 64;
            cp16(st + soff(r, sc), gAh + (size_t)r * K + kof + sc * 8);
        }
        #pragma unroll
        for (int p = 0; p < 2; p++) {
            int r = sr + p * 64;
            cp16(st + 8192 + soff(r, sc), gBh + (size_t)r * K + kof + sc * 8);
        }
    };

    float acc[2][8][4];
    #pragma unroll
    for (int mi = 0; mi < 2; mi++)
        #pragma unroll
        for (int ni = 0; ni < 8; ni++)
            #pragma unroll
            for (int q = 0; q < 4; q++) acc[mi][ni][q] = 0.f;

    #pragma unroll
    for (int s = 0; s < NSTAGE - 1; s++) {
        if (s < nIter) load_stage(s, s * 32);
        cp_commit();
    }

    const int g  = lane >> 3;
    const int lr = lane & 7;

    int csl = 0;
    for (int it = 0; it < nIter; it++) {
        cp_wait<NSTAGE - 2>();
        __syncthreads();
        int ns = it + NSTAGE - 1;
        int lsl = csl - 1; if (lsl < 0) lsl += NSTAGE;
        if (ns < nIter) load_stage(lsl, ns * 32);
        cp_commit();

        const uint32_t st = sb + csl * STAGE_BYTES;
        #pragma unroll
        for (int ks = 0; ks < 2; ks++) {
            const int kc8 = ks * 2;
            uint32_t aH[2][4], bH[8][2];
            #pragma unroll
            for (int mi = 0; mi < 2; mi++) {
                int r  = wm * 32 + mi * 16 + (g & 1) * 8 + lr;
                int ch = kc8 + (g >> 1);
                uint32_t ad = st + soff(r, ch);
                LDSM4(aH[mi][0], aH[mi][1], aH[mi][2], aH[mi][3], ad);
            }
            #pragma unroll
            for (int t = 0; t < 4; t++) {
                int r  = wn * 64 + t * 16 + (g >> 1) * 8 + lr;
                int ch = kc8 + (g & 1);
                uint32_t ad = st + 8192 + soff(r, ch);
                LDSM4(bH[2*t][0], bH[2*t][1], bH[2*t+1][0], bH[2*t+1][1], ad);
            }
            #pragma unroll
            for (int mi = 0; mi < 2; mi++)
                #pragma unroll
                for (int ni = 0; ni < 8; ni++) mma16816(acc[mi][ni], aH[mi], bH[ni]);
        }
        csl++; if (csl == NSTAGE) csl = 0;
    }

    float* Cf = (EPI == 4) ? (float*)Cv + zs * blockIdx.z : (float*)Cv;

    #pragma unroll
    for (int mi = 0; mi < 2; mi++) {
        #pragma unroll
        for (int ni = 0; ni < 8; ni++) {
            int r  = m0 + wm * 32 + mi * 16 + (lane >> 2);
            int cc = n0 + wn * 64 + ni * 8 + (lane & 3) * 2;
            #pragma unroll
            for (int half = 0; half < 2; half++) {
                int rr = r + half * 8;
                float v0 = acc[mi][ni][half * 2];
                float v1 = acc[mi][ni][half * 2 + 1];
                size_t o = (size_t)rr * ldc + cc;
                if (EPI == 3) {
                    ((uint32_t*)Cv)[o >> 1] = pack2(v0, v1);
                } else {
                    *(float2*)(Cf + o) = make_float2(v0, v1);
                }
            }
        }
    }
}

// ---------------- dt_proj: softplus(dtr(bf16) @ W(bf16)^T + b), K=64 ----------------
__global__ void __launch_bounds__(256, 2)
dtproj_kernel(const __nv_bfloat16* __restrict__ dtr,
              const __nv_bfloat16* __restrict__ W,
              const float* __restrict__ bias,
              float* __restrict__ C)
{
    __shared__ __align__(16) char sm[32768];
    const uint32_t sb = smem_u32(sm);

    const int tid  = threadIdx.x;
    const int lane = tid & 31;
    const int wid  = tid >> 5;
    const int wm   = wid >> 1;
    const int wn   = wid & 1;
    const int m0   = blockIdx.x * 128;
    const int n0   = blockIdx.y * 128;

    {
        int r = tid >> 2, ch = tid & 3;
        #pragma unroll
        for (int p = 0; p < 2; p++) {
            int rr = r + p * 64;
            #pragma unroll
            for (int s = 0; s < 2; s++) {
                cp16(sb + s * 8192 + soff(rr, ch),
                     dtr + (size_t)(m0 + rr) * 64 + s * 32 + ch * 8);
                cp16(sb + 16384 + s * 8192 + soff(rr, ch),
                     W + (size_t)(n0 + rr) * 64 + s * 32 + ch * 8);
            }
        }
        cp_commit();
    }
    cp_wait<0>();
    __syncthreads();

    float acc[2][8][4];
    #pragma unroll
    for (int mi = 0; mi < 2; mi++)
        #pragma unroll
        for (int ni = 0; ni < 8; ni++)
            #pragma unroll
            for (int q = 0; q < 4; q++) acc[mi][ni][q] = 0.f;

    const int g  = lane >> 3;
    const int lr = lane & 7;

    #pragma unroll
    for (int ks = 0; ks < 4; ks++) {
        const int sub = ks >> 1;
        const int kc8 = (ks & 1) * 2;
        const uint32_t stA = sb + sub * 8192;
        const uint32_t stB = sb + 16384 + sub * 8192;
        uint32_t aH[2][4], bH[8][2];
        #pragma unroll
        for (int mi = 0; mi < 2; mi++) {
            int r  = wm * 32 + mi * 16 + (g & 1) * 8 + lr;
            int ch = kc8 + (g >> 1);
            LDSM4(aH[mi][0], aH[mi][1], aH[mi][2], aH[mi][3], stA + soff(r, ch));
        }
        #pragma unroll
        for (int t = 0; t < 4; t++) {
            int r  = wn * 64 + t * 16 + (g >> 1) * 8 + lr;
            int ch = kc8 + (g & 1);
            LDSM4(bH[2*t][0], bH[2*t][1], bH[2*t+1][0], bH[2*t+1][1], stB + soff(r, ch));
        }
        #pragma unroll
        for (int mi = 0; mi < 2; mi++)
            #pragma unroll
            for (int ni = 0; ni < 8; ni++) mma16816(acc[mi][ni], aH[mi], bH[ni]);
    }

    #pragma unroll
    for (int mi = 0; mi < 2; mi++) {
        #pragma unroll
        for (int ni = 0; ni < 8; ni++) {
            int r  = m0 + wm * 32 + mi * 16 + (lane >> 2);
            int cc = n0 + wn * 64 + ni * 8 + (lane & 3) * 2;
            #pragma unroll
            for (int half = 0; half < 2; half++) {
                int rr = r + half * 8;
                float v0 = softplusf(acc[mi][ni][half * 2]     + bias[cc]);
                float v1 = softplusf(acc[mi][ni][half * 2 + 1] + bias[cc + 1]);
                *(float2*)(C + (size_t)rr * DI_ + cc) = make_float2(v0, v1);
            }
        }
    }
}

// ---------------- merged convert + transpose kernel ----------------
#define CW_N1 (L_*2*DI_*D_/4)
#define CW_N2 (L_*D_*DI_/4)
#define CW_N3 (L_*DI_*DR_/4)
#define CW_N4 (L_*128*(DI_/4))
#define CW_N5 (128*PCD_/4)
#define CW_TOT (CW_N1+CW_N2+CW_N3+CW_N4+CW_N5)
#define CW_BLK ((CW_TOT+255)/256)
#define TP_W1  ((D_/32)*(PCD_/32))
#define TP_W2  ((D_/32)*(D_/32))

__global__ void convert_all(const float* __restrict__ ipw, __nv_bfloat16* __restrict__ ipwh,
                            const float* __restrict__ opw, __nv_bfloat16* __restrict__ opwh,
                            const float* __restrict__ dtw, __nv_bfloat16* __restrict__ dtwh,
                            const float* __restrict__ xpw, __nv_bfloat16* __restrict__ xpwh,
                            const float* __restrict__ pc,  __nv_bfloat16* __restrict__ pch,
                            const float* __restrict__ w1, __nv_bfloat16* __restrict__ w1t,
                            const float* __restrict__ w2, __nv_bfloat16* __restrict__ w2t) {
    if (blockIdx.x >= CW_BLK) {
        __shared__ float tile[32][33];
        int tb = blockIdx.x - CW_BLK;
        const float* in;
        __nv_bfloat16* out;
        int K, bx, by;
        if (tb < TP_W1) { in = w1; out = w1t; K = PCD_; bx = (tb & 31) * 32; by = (tb >> 5) * 32; }
        else { tb -= TP_W1; in = w2; out = w2t; K = D_; bx = (tb & 31) * 32; by = (tb >> 5) * 32; }
        int tx = threadIdx.x & 31, ty = threadIdx.x >> 5;
        #pragma unroll
        for (int i = 0; i < 32; i += 8)
            tile[ty + i][tx] = in[(size_t)(by + ty + i) * D_ + bx + tx];
        __syncthreads();
        #pragma unroll
        for (int i = 0; i < 32; i += 8)
            out[(size_t)(bx + ty + i) * K + by + tx] = __float2bfloat16(tile[tx][ty + i]);
        return;
    }
    int i = blockIdx.x * 256 + threadIdx.x;
    if (i < CW_N1) {
        cvt_store4(((const float4*)ipw)[i], ipwh, i);
    } else if (i < CW_N1 + CW_N2) {
        int j = i - CW_N1;
        cvt_store4(((const float4*)opw)[j], opwh, j);
    } else if (i < CW_N1 + CW_N2 + CW_N3) {
        int j = i - (CW_N1 + CW_N2);
        cvt_store4(((const float4*)dtw)[j], dtwh, j);
    } else if (i < CW_N1 + CW_N2 + CW_N3 + CW_N4) {
        int j = i - (CW_N1 + CW_N2 + CW_N3);
        int k4   = j % (DI_/4);
        int nrow = (j / (DI_/4)) % 128;
        int lay  = j / (128 * (DI_/4));
        float4 v = make_float4(0.f, 0.f, 0.f, 0.f);
        if (nrow < 96)
            v = ((const float4*)xpw)[(size_t)(lay * 96 + nrow) * (DI_/4) + k4];
        cvt_store4(v, xpwh, j);
    } else if (i < CW_TOT) {
        int j = i - (CW_N1 + CW_N2 + CW_N3 + CW_N4);
        cvt_store4(((const float4*)pc)[j], pch, j);
    }
}

// reduce 6 prepend-gemm1 partials + silu + cvt -> bf16
__global__ void silu_cvt_red(const float* __restrict__ parts, __nv_bfloat16* __restrict__ out) {
    int i = blockIdx.x * 256 + threadIdx.x;
    if (i >= 128*D_/4) return;
    float4 v = make_float4(0.f,0.f,0.f,0.f);
    #pragma unroll
    for (int z = 0; z < 6; z++)
        v = f4add(v, ((const float4*)parts)[(size_t)z*(128*D_/4) + i]);
    v = make_float4(siluf(v.x), siluf(v.y), siluf(v.z), siluf(v.w));
    cvt_store4(v, out, i);
}

// reduce 16 x_proj partials -> dtr bf16 [M,64] + bc fp32 [M,32]
__global__ void reduce_xdbl(const float* __restrict__ parts,
                            __nv_bfloat16* __restrict__ dtr,
                            float* __restrict__ bc) {
    int i = blockIdx.x * 256 + threadIdx.x;
    if (i >= M_ * 24) return;
    int m = i / 24, c4 = i % 24;
    float4 acc = make_float4(0.f,0.f,0.f,0.f);
    #pragma unroll
    for (int z = 0; z < 16; z++)
        acc = f4add(acc, ((const float4*)parts)[(size_t)z*(M_*128/4) + (size_t)m*32 + c4]);
    if (c4 < 16) cvt_store4(acc, dtr, (size_t)m*16 + c4);
    else         ((float4*)bc)[(size_t)m*8 + (c4 - 16)] = acc;
}

// ---------------- fused build_h (8-way partial reduce) + rmsnorm (layer 0) ----------------
__global__ void build_rms_kernel(const float* __restrict__ pp2,
                                 const float* __restrict__ x,
                                 const float* __restrict__ w,
                                 float* __restrict__ h,
                                 __nv_bfloat16* __restrict__ oh) {
    int row = blockIdx.x;
    int b = row / T_;
    int t = row % T_;
    int tid = threadIdx.x;
    float4 x4;
    if (t < P_) {
        x4 = make_float4(0.f,0.f,0.f,0.f);
        size_t o = (size_t)(b*P_ + t)*(D_/4) + tid;
        #pragma unroll
        for (int z = 0; z < 8; z++)
            x4 = f4add(x4, ((const float4*)pp2)[(size_t)z*(128*D_/4) + o]);
    } else {
        x4 = ((const float4*)(x + (size_t)(b*S_ + (t - P_))*D_))[tid];
    }
    ((float4*)(h + (size_t)row*D_))[tid] = x4;
    float s = x4.x*x4.x + x4.y*x4.y + x4.z*x4.z + x4.w*x4.w;
    #pragma unroll
    for (int o = 16; o; o >>= 1) s += __shfl_xor_sync(0xffffffffu, s, o);
    __shared__ float ws[8];
    __shared__ float scale_s;
    if ((tid & 31) == 0) ws[tid >> 5] = s;
    __syncthreads();
    if (tid == 0) {
        float tt = 0.f;
        #pragma unroll
        for (int i = 0; i < 8; i++) tt += ws[i];
        scale_s = rsqrtf(tt / (float)D_ + 1e-5f);
    }
    __syncthreads();
    float sc = scale_s;
    float4 wv = ((const float4*)w)[tid];
    float4 v = make_float4(x4.x*sc*wv.x, x4.y*sc*wv.y, x4.z*sc*wv.z, x4.w*sc*wv.w);
    cvt_store4(v, oh, (size_t)row*(D_/4) + tid);
}

// rmsnorm with fused out_proj 2-partial accumulate; writes back h
__global__ void rmsnorm_acc_kernel(float* __restrict__ h,
                                   const float* __restrict__ parts,
                                   const float* __restrict__ w,
                                   __nv_bfloat16* __restrict__ oh) {
    int row = blockIdx.x;
    int tid = threadIdx.x;
    size_t o = (size_t)row*(D_/4) + tid;
    float4 x4 = ((const float4*)h)[o];
    x4 = f4add(x4, ((const float4*)parts)[o]);
    x4 = f4add(x4, ((const float4*)parts)[(size_t)(M_*D_/4) + o]);
    ((float4*)h)[o] = x4;
    float s = x4.x*x4.x + x4.y*x4.y + x4.z*x4.z + x4.w*x4.w;
    #pragma unroll
    for (int q = 16; q; q >>= 1) s += __shfl_xor_sync(0xffffffffu, s, q);
    __shared__ float ws[8];
    __shared__ float scale_s;
    if ((tid & 31) == 0) ws[tid >> 5] = s;
    __syncthreads();
    if (tid == 0) {
        float t = 0.f;
        #pragma unroll
        for (int i = 0; i < 8; i++) t += ws[i];
        scale_s = rsqrtf(t / (float)D_ + 1e-5f);
    }
    __syncthreads();
    float sc = scale_s;
    float4 wv = ((const float4*)w)[tid];
    float4 v = make_float4(x4.x*sc*wv.x, x4.y*sc*wv.y, x4.z*sc*wv.z, x4.w*sc*wv.w);
    cvt_store4(v, oh, o);
}

// final rmsnorm with fused out_proj 2-partial accumulate
__global__ void final_acc_kernel(const float* __restrict__ h,
                                 const float* __restrict__ parts,
                                 const float* __restrict__ w,
                                 float* __restrict__ out) {
    int row = blockIdx.x;
    int b = row >> 9;
    int t = row & 511;
    int hrow = b*T_ + P_ + t;
    int tid = threadIdx.x;
    size_t o = (size_t)hrow*(D_/4) + tid;
    float4 x4 = ((const float4*)h)[o];
    x4 = f4add(x4, ((const float4*)parts)[o]);
    x4 = f4add(x4, ((const float4*)parts)[(size_t)(M_*D_/4) + o]);
    float s = x4.x*x4.x + x4.y*x4.y + x4.z*x4.z + x4.w*x4.w;
    #pragma unroll
    for (int q = 16; q; q >>= 1) s += __shfl_xor_sync(0xffffffffu, s, q);
    __shared__ float ws[8];
    __shared__ float scale_s;
    if ((tid & 31) == 0) ws[tid >> 5] = s;
    __syncthreads();
    if (tid == 0) {
        float tt = 0.f;
        #pragma unroll
        for (int i = 0; i < 8; i++) tt += ws[i];
        scale_s = rsqrtf(tt / (float)D_ + 1e-5f);
    }
    __syncthreads();
    float sc = scale_s;
    float4 wv = ((const float4*)w)[tid];
    float4 o4 = make_float4(x4.x*sc*wv.x, x4.y*sc*wv.y, x4.z*sc*wv.z, x4.w*sc*wv.w);
    ((float4*)(out + (size_t)row*D_))[tid] = o4;
}

// depthwise causal conv (DC=4) + silu; reads bf16 xz, writes bf16 xi
__global__ void conv_silu4(const __nv_bfloat16* __restrict__ xzh,
                           const float* __restrict__ cw,
                           const float* __restrict__ cb,
                           __nv_bfloat16* __restrict__ xih) {
    int idx = blockIdx.x * blockDim.x + threadIdx.x;
    if (idx >= M_*(DI_/4)) return;

    int e4 = idx % (DI_/4);
    int m  = idx / (DI_/4);
    int t  = m % T_;
    float4 w0 = ((const float4*)cw)[e4*4+0];
    float4 w1 = ((const float4*)cw)[e4*4+1];
    float4 w2 = ((const float4*)cw)[e4*4+2];
    float4 w3 = ((const float4*)cw)[e4*4+3];
    float4 acc = ((const float4*)cb)[e4];
    const float* wj[4] = { (const float*)&w0, (const float*)&w1,
                           (const float*)&w2, (const float*)&w3 };
    #pragma unroll
    for (int j = 0; j < 4; j++) {
        int tt = t - 3 + j;
        if (tt >= 0) {
            uint2 raw = *(const uint2*)(xzh + (size_t)(m - 3 + j)*(2*DI_) + e4*4);
            __nv_bfloat162 p0 = *(__nv_bfloat162*)&raw.x;
            __nv_bfloat162 p1 = *(__nv_bfloat162*)&raw.y;
            acc.x = fmaf(bf2f(p0.x), wj[0][j], acc.x);
            acc.y = fmaf(bf2f(p0.y), wj[1][j], acc.y);
            acc.z = fmaf(bf2f(p1.x), wj[2][j], acc.z);
            acc.w = fmaf(bf2f(p1.y), wj[3][j], acc.w);
        }
    }
    float4 v = make_float4(siluf(acc.x), siluf(acc.y), siluf(acc.z), siluf(acc.w));
    cvt_store4(v, xih, idx);
}

// ---------------- selective scan, double-buffered cp.async staging ----------------
// block = 256 threads (8 warps), 16 channels; warp w computes channels 2w, 2w+1.
__global__ void __launch_bounds__(256)
scan_kernel(const __nv_bfloat16* __restrict__ xzh,
            const __nv_bfloat16* __restrict__ xih,
            const float* __restrict__ bc,
            const float* __restrict__ dt,
            const float* __restrict__ A_log,
            const float* __restrict__ Dp,
            __nv_bfloat16* __restrict__ yh) {
    __shared__ __align__(16) float sdt[2][16][16], sB[2][16][16], sC[2][16][16];
    __shared__ __align__(16) __nv_bfloat16 sxi[2][16][16], sz[2][16][16];
    __shared__ uint32_t sy[16][8];

    const int tid  = threadIdx.x;
    const int lane = tid & 31;
    const int warp = tid >> 5;
    const int blk  = blockIdx.x;
    const int b    = blk >> 7;
    const int e0   = (blk & 127) * 16;
    const int m0   = b * T_;

    const int cloc = 2 * warp + (lane >> 4);
    const int s    = lane & 15;
    const int e    = e0 + cloc;

    const float A  = -expf(A_log[(size_t)e*DS_ + s]);
    const float Dv = Dp[e];
    float h = 0.f;

    auto load_chunk = [&](int buf, int tb) {
        if (tid < 64) {
            int r = tid >> 2, c = tid & 3;
            cp16(smem_u32(&sdt[buf][r][c*4]), dt + (size_t)(m0 + tb + r)*DI_ + e0 + c*4);
        } else if (tid < 128) {
            int t2 = tid - 64;
            int r = t2 >> 2, c = t2 & 3;
            cp16(smem_u32(&sB[buf][r][c*4]), bc + (size_t)(m0 + tb + r)*32 + c*4);
        } else if (tid < 192) {
            int t2 = tid - 128;
            int r = t2 >> 2, c = t2 & 3;
            cp16(smem_u32(&sC[buf][r][c*4]), bc + (size_t)(m0 + tb + r)*32 + 16 + c*4);
        } else if (tid < 224) {
            int t2 = tid - 192;
            int r = t2 >> 1, c = t2 & 1;
            cp16(smem_u32(&sxi[buf][r][c*8]), xih + (size_t)(m0 + tb + r)*DI_ + e0 + c*8);
        } else {
            int t2 = tid - 224;
            int r = t2 >> 1, c = t2 & 1;
            cp16(smem_u32(&sz[buf][r][c*8]), xzh + (size_t)(m0 + tb + r)*(2*DI_) + DI_ + e0 + c*8);
        }
    };

    load_chunk(0, 0);
    cp_commit();

    for (int ci = 0; ci < T_/16; ci++) {
        if (ci + 1 < T_/16) load_chunk((ci + 1) & 1, (ci + 1) * 16);
        cp_commit();
        cp_wait<1>();
        __syncthreads();

        const int buf = ci & 1;
        float p[16];
        #pragma unroll
        for (int j = 0; j < 16; j++) {
            float dtv = sdt[buf][j][cloc];
            float dA  = __expf(dtv * A);
            h = fmaf(dA, h, dtv * sB[buf][j][s] * bf2f(sxi[buf][j][cloc]));
            p[j] = h * sC[buf][j][s];
        }
        #pragma unroll
        for (int o = 8; o >= 1; o >>= 1)
            #pragma unroll
            for (int j = 0; j < 16; j++)
                p[j] += __shfl_xor_sync(0xffffffffu, p[j], o);
        #pragma unroll
        for (int j = 0; j < 16; j++) {
            float val = (p[j] + bf2f(sxi[buf][j][cloc]) * Dv) * siluf(bf2f(sz[buf][j][cloc]));
            float v1  = __shfl_down_sync(0xffffffffu, val, 16);
            if (lane == 0) sy[j][warp] = pack2(val, v1);
        }
        __syncthreads();

        if (tid < 128) {
            int t = tid >> 3, q = tid & 7;
            ((uint32_t*)yh)[((size_t)(m0 + ci*16 + t)*DI_ + e0) / 2 + q] = sy[t][q];
        }
        __syncthreads();
    }
}

// ---------------- host orchestration ----------------
extern "C" void kernel_launch(void* const* d_in, const int* in_sizes, int n_in,
                              void* d_out, int out_size) {
    (void)in_sizes; (void)n_in; (void)out_size;
    const float* x      = (const float*)d_in[0];
    const float* pc     = (const float*)d_in[1];
    const float* w1     = (const float*)d_in[2];
    const float* w2     = (const float*)d_in[3];
    const float* norm_w = (const float*)d_in[4];
    const float* ipw    = (const float*)d_in[5];
    const float* cw     = (const float*)d_in[6];
    const float* cb     = (const float*)d_in[7];
    const float* xpw    = (const float*)d_in[8];
    const float* dtw    = (const float*)d_in[9];
    const float* dtb    = (const float*)d_in[10];
    const float* A_log  = (const float*)d_in[11];
    const float* Dparam = (const float*)d_in[12];
    const float* opw    = (const float*)d_in[13];
    const float* fnw    = (const float*)d_in[14];

    float *h, *dtp, *bcp, *part16, *part2, *pp1, *pp2;
    cudaGetSymbolAddress((void**)&h,      g_h);
    cudaGetSymbolAddress((void**)&dtp,    g_dt);
    cudaGetSymbolAddress((void**)&bcp,    g_bc);
    cudaGetSymbolAddress((void**)&part16, g_part16);
    cudaGetSymbolAddress((void**)&part2,  g_part2);
    cudaGetSymbolAddress((void**)&pp1,    g_pp1);
    cudaGetSymbolAddress((void**)&pp2,    g_pp2);

    __nv_bfloat16 *xzh, *xnh, *xih, *yh, *dtrh, *ipwh, *opwh, *xpwh, *dtwh, *pch, *p1h, *w1t, *w2t;
    cudaGetSymbolAddress((void**)&xzh,  g_xz_h);
    cudaGetSymbolAddress((void**)&xnh,  g_xn_h);
    cudaGetSymbolAddress((void**)&xih,  g_xi_h);
    cudaGetSymbolAddress((void**)&yh,   g_y_h);
    cudaGetSymbolAddress((void**)&dtrh, g_dtr_h);
    cudaGetSymbolAddress((void**)&ipwh, g_ipw_h);
    cudaGetSymbolAddress((void**)&opwh, g_opw_h);
    cudaGetSymbolAddress((void**)&xpwh, g_xpw_h);
    cudaGetSymbolAddress((void**)&dtwh, g_dtw_h);
    cudaGetSymbolAddress((void**)&pch,  g_pc_h);
    cudaGetSymbolAddress((void**)&p1h,  g_p1_h);
    cudaGetSymbolAddress((void**)&w1t,  g_w1t);
    cudaGetSymbolAddress((void**)&w2t,  g_w2t);

    cudaFuncSetAttribute(tc_gemm<3>, cudaFuncAttributeMaxDynamicSharedMemorySize, GEMM_DYN);
    cudaFuncSetAttribute(tc_gemm<4>, cudaFuncAttributeMaxDynamicSharedMemorySize, GEMM_DYN);

    // ---- converts + transposes (1 launch) ----
    convert_all<<<CW_BLK + TP_W1 + TP_W2, 256>>>(ipw, ipwh, opw, opwh, dtw, dtwh,
                                                 xpw, xpwh, pc, pch, w1, w1t, w2, w2t);

    // ---- prepend MLP, split-K partials (no atomics) ----
    tc_gemm<4><<<dim3(1, 8, 6), 256, GEMM_DYN>>>(pch, w1t, pp1, PCD_, D_, (size_t)128*D_);
    silu_cvt_red<<<(128*D_/4+255)/256, 256>>>(pp1, p1h);
    tc_gemm<4><<<dim3(1, 8, 8), 256, GEMM_DYN>>>(p1h, w2t, pp2, D_, D_, (size_t)128*D_);
    build_rms_kernel<<<M_, 256>>>(pp2, x, norm_w, h, xnh);

    // ---- 4 mamba layers ----
    for (int l = 0; l < L_; l++) {
        // xz = xn @ in_proj_w^T -> bf16  (288 CTAs)
        tc_gemm<3><<<dim3(9, 32, 1), 256, GEMM_DYN>>>(
            xnh, ipwh + (size_t)l*2*DI_*D_, xzh, D_, 2*DI_, 0);

        conv_silu4<<<(M_*(DI_/4)+255)/256, 256>>>(
            xzh, cw + (size_t)l*DI_*4, cb + (size_t)l*DI_, xih);

        // x_proj partials (144 CTAs, split-K=16)
        tc_gemm<4><<<dim3(9, 1, 16), 256, GEMM_DYN>>>(
            xih, xpwh + (size_t)l*128*DI_, part16, DI_, 128, (size_t)M_*128);
        reduce_xdbl<<<(M_*24+255)/256, 256>>>(part16, dtrh, bcp);

        // dt = softplus(dtr @ dt_proj_w^T + b)
        dtproj_kernel<<<dim3(9, 16), 256>>>(
            dtrh, dtwh + (size_t)l*DI_*DR_, dtb + (size_t)l*DI_, dtp);

        // selective scan + gate -> y bf16 (double-buffered staging, 256 CTAs)
        scan_kernel<<<B_*(DI_/16), 256>>>(
            xzh, xih, bcp, dtp,
            A_log + (size_t)l*DI_*DS_, Dparam + (size_t)l*DI_, yh);

        // out_proj partials (144 CTAs, split-K=2)
        tc_gemm<4><<<dim3(9, 8, 2), 256, GEMM_DYN>>>(
            yh, opwh + (size_t)l*D_*DI_, part2, DI_, D_, (size_t)M_*D_);

        if (l < L_ - 1)
            rmsnorm_acc_kernel<<<M_, 256>>>(h, part2, norm_w + (size_t)(l+1)*D_, xnh);
        else
            final_acc_kernel<<<B_*S_, 256>>>(h, part2, fnw, (float*)d_out);
    }
}

// round 17
// speedup vs baseline: 1.1506x; 1.0606x over previous
#include <cuda_runtime.h>
#include <cuda_bf16.h>
#include <math.h>
#include <stdint.h>

#define B_   2
#define S_   512
#define P_   64
#define T_   576
#define D_   1024
#define L_   4
#define DI_  2048
#define DS_  16
#define DR_  64
#define PCD_ 768
#define M_   (B_*T_)   // 1152

// ---------------- static scratch ----------------
__device__ float g_h   [M_*D_];
__device__ float g_dt  [M_*DI_];
__device__ float g_bc  [M_*32];         // [B(16) | C(16)] per row, fp32

// split-K partial buffers (no atomics)
__device__ float g_part16[16*M_*128];   // x_proj partials (ldc padded to 128)
__device__ float g_part2 [2*M_*D_];     // out_proj partials
__device__ float g_pp1   [6*128*D_];    // prepend gemm1 partials
__device__ float g_pp2   [8*128*D_];    // prepend gemm2 partials

__device__ __align__(16) __nv_bfloat16 g_xz_h [M_*2*DI_];
__device__ __align__(16) __nv_bfloat16 g_xn_h [M_*D_];
__device__ __align__(16) __nv_bfloat16 g_xi_h [M_*DI_];
__device__ __align__(16) __nv_bfloat16 g_y_h  [M_*DI_];
__device__ __align__(16) __nv_bfloat16 g_dtr_h[M_*DR_];
__device__ __align__(16) __nv_bfloat16 g_pc_h [128*PCD_];
__device__ __align__(16) __nv_bfloat16 g_p1_h [128*D_];

// weights: bf16
__device__ __align__(16) __nv_bfloat16 g_ipw_h[L_*2*DI_*D_];
__device__ __align__(16) __nv_bfloat16 g_opw_h[L_*D_*DI_];
__device__ __align__(16) __nv_bfloat16 g_xpw_h[L_*128*DI_];   // N padded 96->128
__device__ __align__(16) __nv_bfloat16 g_dtw_h[L_*DI_*DR_];
__device__ __align__(16) __nv_bfloat16 g_w1t  [D_*PCD_];      // w1^T bf16
__device__ __align__(16) __nv_bfloat16 g_w2t  [D_*D_];        // w2^T bf16

// ---------------- helpers ----------------
__device__ __forceinline__ float siluf(float x) { return x / (1.f + __expf(-x)); }
__device__ __forceinline__ float softplusf(float x) {
    return x > 20.f ? x : log1pf(__expf(x));
}
__device__ __forceinline__ uint32_t smem_u32(const void* p) {
    uint32_t a;
    asm("{ .reg .u64 t; cvta.to.shared.u64 t, %1; cvt.u32.u64 %0, t; }" : "=r"(a) : "l"(p));
    return a;
}
__device__ __forceinline__ uint32_t pack2(float a, float b) {
    __nv_bfloat162 t = __floats2bfloat162_rn(a, b);
    return *(uint32_t*)&t;
}
__device__ __forceinline__ void cvt_store4(float4 v, __nv_bfloat16* __restrict__ hp, size_t i4) {
    uint2 o;
    o.x = pack2(v.x, v.y);
    o.y = pack2(v.z, v.w);
    ((uint2*)hp)[i4] = o;
}
__device__ __forceinline__ float bf2f(__nv_bfloat16 v) { return __bfloat162float(v); }
__device__ __forceinline__ float4 f4add(float4 a, float4 b) {
    return make_float4(a.x+b.x, a.y+b.y, a.z+b.z, a.w+b.w);
}

// ---------------- async copy / ldmatrix / mma primitives ----------------
__device__ __forceinline__ void cp16(uint32_t s, const void* g) {
    asm volatile("cp.async.ca.shared.global [%0], [%1], 16;" :: "r"(s), "l"(g));
}
// L2-only variant for streamed GEMM staging (no L1 reuse)
__device__ __forceinline__ void cp16cg(uint32_t s, const void* g) {
    asm volatile("cp.async.cg.shared.global [%0], [%1], 16;" :: "r"(s), "l"(g));
}
__device__ __forceinline__ void cp_commit() {
    asm volatile("cp.async.commit_group;" ::: "memory");
}
template<int N>
__device__ __forceinline__ void cp_wait() {
    asm volatile("cp.async.wait_group %0;" :: "n"(N) : "memory");
}
#define LDSM4(r0,r1,r2,r3,addr) \
    asm volatile("ldmatrix.sync.aligned.m8n8.x4.shared.b16 {%0,%1,%2,%3}, [%4];" \
        : "=r"(r0),"=r"(r1),"=r"(r2),"=r"(r3) : "r"(addr))

__device__ __forceinline__ void mma16816(float* c, const uint32_t* a, const uint32_t* b) {
    asm volatile(
        "mma.sync.aligned.m16n8k16.row.col.f32.bf16.bf16.f32 "
        "{%0,%1,%2,%3}, {%4,%5,%6,%7}, {%8,%9}, {%0,%1,%2,%3};"
        : "+f"(c[0]), "+f"(c[1]), "+f"(c[2]), "+f"(c[3])
        : "r"(a[0]), "r"(a[1]), "r"(a[2]), "r"(a[3]), "r"(b[0]), "r"(b[1]));
}

__device__ __forceinline__ uint32_t soff(int r, int ch) {
    return (uint32_t)(r * 64 + ((ch ^ ((r >> 1) & 3)) << 4));
}

// ---------------- pipelined bf16 tensor-core GEMM ----------------
// EPI: 0 = store f32, 3 = store bf16, 4 = store f32 partial at + z*zs
#define STAGE_BYTES 16384   // AH 8K | BH 8K
#define NSTAGE 5
#define GEMM_DYN (NSTAGE*STAGE_BYTES + 128)

template<int EPI>
__global__ void __launch_bounds__(256, 2)
tc_gemm(const __nv_bfloat16* __restrict__ Ah,
        const __nv_bfloat16* __restrict__ Bh,
        void* __restrict__ Cv,
        int K, int ldc, size_t zs)
{
    extern __shared__ __align__(16) char dsm[];
    const uint32_t sb = (smem_u32(dsm) + 127u) & ~127u;

    const int tid  = threadIdx.x;
    const int lane = tid & 31;
    const int wid  = tid >> 5;
    const int wm   = wid >> 1;
    const int wn   = wid & 1;
    const int m0   = blockIdx.x * 128;
    const int n0   = blockIdx.y * 128;
    const int kPer = K / gridDim.z;
    const int kBeg = blockIdx.z * kPer;
    const int nIter = kPer >> 5;

    const __nv_bfloat16* gAh = Ah + (size_t)m0 * K + kBeg;
    const __nv_bfloat16* gBh = Bh + (size_t)n0 * K + kBeg;

    const int sr = tid >> 2;
    const int sc = tid & 3;

    auto load_stage = [&](int slot, int kof) {
        const uint32_t st = sb + slot * STAGE_BYTES;
        #pragma unroll
        for (int p = 0; p < 2; p++) {
            int r = sr + p * 64;
            cp16cg(st + soff(r, sc), gAh + (size_t)r * K + kof + sc * 8);
        }
        #pragma unroll
        for (int p = 0; p < 2; p++) {
            int r = sr + p * 64;
            cp16cg(st + 8192 + soff(r, sc), gBh + (size_t)r * K + kof + sc * 8);
        }
    };

    float acc[2][8][4];
    #pragma unroll
    for (int mi = 0; mi < 2; mi++)
        #pragma unroll
        for (int ni = 0; ni < 8; ni++)
            #pragma unroll
            for (int q = 0; q < 4; q++) acc[mi][ni][q] = 0.f;

    #pragma unroll
    for (int s = 0; s < NSTAGE - 1; s++) {
        if (s < nIter) load_stage(s, s * 32);
        cp_commit();
    }

    const int g  = lane >> 3;
    const int lr = lane & 7;

    int csl = 0;
    for (int it = 0; it < nIter; it++) {
        cp_wait<NSTAGE - 2>();
        __syncthreads();
        int ns = it + NSTAGE - 1;
        int lsl = csl - 1; if (lsl < 0) lsl += NSTAGE;
        if (ns < nIter) load_stage(lsl, ns * 32);
        cp_commit();

        const uint32_t st = sb + csl * STAGE_BYTES;
        #pragma unroll
        for (int ks = 0; ks < 2; ks++) {
            const int kc8 = ks * 2;
            uint32_t aH[2][4], bH[8][2];
            #pragma unroll
            for (int mi = 0; mi < 2; mi++) {
                int r  = wm * 32 + mi * 16 + (g & 1) * 8 + lr;
                int ch = kc8 + (g >> 1);
                uint32_t ad = st + soff(r, ch);
                LDSM4(aH[mi][0], aH[mi][1], aH[mi][2], aH[mi][3], ad);
            }
            #pragma unroll
            for (int t = 0; t < 4; t++) {
                int r  = wn * 64 + t * 16 + (g >> 1) * 8 + lr;
                int ch = kc8 + (g & 1);
                uint32_t ad = st + 8192 + soff(r, ch);
                LDSM4(bH[2*t][0], bH[2*t][1], bH[2*t+1][0], bH[2*t+1][1], ad);
            }
            #pragma unroll
            for (int mi = 0; mi < 2; mi++)
                #pragma unroll
                for (int ni = 0; ni < 8; ni++) mma16816(acc[mi][ni], aH[mi], bH[ni]);
        }
        csl++; if (csl == NSTAGE) csl = 0;
    }

    float* Cf = (EPI == 4) ? (float*)Cv + zs * blockIdx.z : (float*)Cv;

    #pragma unroll
    for (int mi = 0; mi < 2; mi++) {
        #pragma unroll
        for (int ni = 0; ni < 8; ni++) {
            int r  = m0 + wm * 32 + mi * 16 + (lane >> 2);
            int cc = n0 + wn * 64 + ni * 8 + (lane & 3) * 2;
            #pragma unroll
            for (int half = 0; half < 2; half++) {
                int rr = r + half * 8;
                float v0 = acc[mi][ni][half * 2];
                float v1 = acc[mi][ni][half * 2 + 1];
                size_t o = (size_t)rr * ldc + cc;
                if (EPI == 3) {
                    ((uint32_t*)Cv)[o >> 1] = pack2(v0, v1);
                } else {
                    *(float2*)(Cf + o) = make_float2(v0, v1);
                }
            }
        }
    }
}

// ---------------- dt_proj: softplus(dtr(bf16) @ W(bf16)^T + b), K=64 ----------------
__global__ void __launch_bounds__(256, 2)
dtproj_kernel(const __nv_bfloat16* __restrict__ dtr,
              const __nv_bfloat16* __restrict__ W,
              const float* __restrict__ bias,
              float* __restrict__ C)
{
    __shared__ __align__(16) char sm[32768];
    const uint32_t sb = smem_u32(sm);

    const int tid  = threadIdx.x;
    const int lane = tid & 31;
    const int wid  = tid >> 5;
    const int wm   = wid >> 1;
    const int wn   = wid & 1;
    const int m0   = blockIdx.x * 128;
    const int n0   = blockIdx.y * 128;

    {
        int r = tid >> 2, ch = tid & 3;
        #pragma unroll
        for (int p = 0; p < 2; p++) {
            int rr = r + p * 64;
            #pragma unroll
            for (int s = 0; s < 2; s++) {
                cp16(sb + s * 8192 + soff(rr, ch),
                     dtr + (size_t)(m0 + rr) * 64 + s * 32 + ch * 8);
                cp16(sb + 16384 + s * 8192 + soff(rr, ch),
                     W + (size_t)(n0 + rr) * 64 + s * 32 + ch * 8);
            }
        }
        cp_commit();
    }
    cp_wait<0>();
    __syncthreads();

    float acc[2][8][4];
    #pragma unroll
    for (int mi = 0; mi < 2; mi++)
        #pragma unroll
        for (int ni = 0; ni < 8; ni++)
            #pragma unroll
            for (int q = 0; q < 4; q++) acc[mi][ni][q] = 0.f;

    const int g  = lane >> 3;
    const int lr = lane & 7;

    #pragma unroll
    for (int ks = 0; ks < 4; ks++) {
        const int sub = ks >> 1;
        const int kc8 = (ks & 1) * 2;
        const uint32_t stA = sb + sub * 8192;
        const uint32_t stB = sb + 16384 + sub * 8192;
        uint32_t aH[2][4], bH[8][2];
        #pragma unroll
        for (int mi = 0; mi < 2; mi++) {
            int r  = wm * 32 + mi * 16 + (g & 1) * 8 + lr;
            int ch = kc8 + (g >> 1);
            LDSM4(aH[mi][0], aH[mi][1], aH[mi][2], aH[mi][3], stA + soff(r, ch));
        }
        #pragma unroll
        for (int t = 0; t < 4; t++) {
            int r  = wn * 64 + t * 16 + (g >> 1) * 8 + lr;
            int ch = kc8 + (g & 1);
            LDSM4(bH[2*t][0], bH[2*t][1], bH[2*t+1][0], bH[2*t+1][1], stB + soff(r, ch));
        }
        #pragma unroll
        for (int mi = 0; mi < 2; mi++)
            #pragma unroll
            for (int ni = 0; ni < 8; ni++) mma16816(acc[mi][ni], aH[mi], bH[ni]);
    }

    #pragma unroll
    for (int mi = 0; mi < 2; mi++) {
        #pragma unroll
        for (int ni = 0; ni < 8; ni++) {
            int r  = m0 + wm * 32 + mi * 16 + (lane >> 2);
            int cc = n0 + wn * 64 + ni * 8 + (lane & 3) * 2;
            #pragma unroll
            for (int half = 0; half < 2; half++) {
                int rr = r + half * 8;
                float v0 = softplusf(acc[mi][ni][half * 2]     + bias[cc]);
                float v1 = softplusf(acc[mi][ni][half * 2 + 1] + bias[cc + 1]);
                *(float2*)(C + (size_t)rr * DI_ + cc) = make_float2(v0, v1);
            }
        }
    }
}

// ---------------- merged convert + transpose kernel ----------------
#define CW_N1 (L_*2*DI_*D_/4)
#define CW_N2 (L_*D_*DI_/4)
#define CW_N3 (L_*DI_*DR_/4)
#define CW_N4 (L_*128*(DI_/4))
#define CW_N5 (128*PCD_/4)
#define CW_TOT (CW_N1+CW_N2+CW_N3+CW_N4+CW_N5)
#define CW_BLK ((CW_TOT+255)/256)
#define TP_W1  ((D_/32)*(PCD_/32))
#define TP_W2  ((D_/32)*(D_/32))

__global__ void convert_all(const float* __restrict__ ipw, __nv_bfloat16* __restrict__ ipwh,
                            const float* __restrict__ opw, __nv_bfloat16* __restrict__ opwh,
                            const float* __restrict__ dtw, __nv_bfloat16* __restrict__ dtwh,
                            const float* __restrict__ xpw, __nv_bfloat16* __restrict__ xpwh,
                            const float* __restrict__ pc,  __nv_bfloat16* __restrict__ pch,
                            const float* __restrict__ w1, __nv_bfloat16* __restrict__ w1t,
                            const float* __restrict__ w2, __nv_bfloat16* __restrict__ w2t) {
    if (blockIdx.x >= CW_BLK) {
        __shared__ float tile[32][33];
        int tb = blockIdx.x - CW_BLK;
        const float* in;
        __nv_bfloat16* out;
        int K, bx, by;
        if (tb < TP_W1) { in = w1; out = w1t; K = PCD_; bx = (tb & 31) * 32; by = (tb >> 5) * 32; }
        else { tb -= TP_W1; in = w2; out = w2t; K = D_; bx = (tb & 31) * 32; by = (tb >> 5) * 32; }
        int tx = threadIdx.x & 31, ty = threadIdx.x >> 5;
        #pragma unroll
        for (int i = 0; i < 32; i += 8)
            tile[ty + i][tx] = in[(size_t)(by + ty + i) * D_ + bx + tx];
        __syncthreads();
        #pragma unroll
        for (int i = 0; i < 32; i += 8)
            out[(size_t)(bx + ty + i) * K + by + tx] = __float2bfloat16(tile[tx][ty + i]);
        return;
    }
    int i = blockIdx.x * 256 + threadIdx.x;
    if (i < CW_N1) {
        cvt_store4(((const float4*)ipw)[i], ipwh, i);
    } else if (i < CW_N1 + CW_N2) {
        int j = i - CW_N1;
        cvt_store4(((const float4*)opw)[j], opwh, j);
    } else if (i < CW_N1 + CW_N2 + CW_N3) {
        int j = i - (CW_N1 + CW_N2);
        cvt_store4(((const float4*)dtw)[j], dtwh, j);
    } else if (i < CW_N1 + CW_N2 + CW_N3 + CW_N4) {
        int j = i - (CW_N1 + CW_N2 + CW_N3);
        int k4   = j % (DI_/4);
        int nrow = (j / (DI_/4)) % 128;
        int lay  = j / (128 * (DI_/4));
        float4 v = make_float4(0.f, 0.f, 0.f, 0.f);
        if (nrow < 96)
            v = ((const float4*)xpw)[(size_t)(lay * 96 + nrow) * (DI_/4) + k4];
        cvt_store4(v, xpwh, j);
    } else if (i < CW_TOT) {
        int j = i - (CW_N1 + CW_N2 + CW_N3 + CW_N4);
        cvt_store4(((const float4*)pc)[j], pch, j);
    }
}

// reduce 6 prepend-gemm1 partials + silu + cvt -> bf16
__global__ void silu_cvt_red(const float* __restrict__ parts, __nv_bfloat16* __restrict__ out) {
    int i = blockIdx.x * 256 + threadIdx.x;
    if (i >= 128*D_/4) return;
    float4 v = make_float4(0.f,0.f,0.f,0.f);
    #pragma unroll
    for (int z = 0; z < 6; z++)
        v = f4add(v, ((const float4*)parts)[(size_t)z*(128*D_/4) + i]);
    v = make_float4(siluf(v.x), siluf(v.y), siluf(v.z), siluf(v.w));
    cvt_store4(v, out, i);
}

// reduce 16 x_proj partials -> dtr bf16 [M,64] + bc fp32 [M,32]
__global__ void reduce_xdbl(const float* __restrict__ parts,
                            __nv_bfloat16* __restrict__ dtr,
                            float* __restrict__ bc) {
    int i = blockIdx.x * 256 + threadIdx.x;
    if (i >= M_ * 24) return;
    int m = i / 24, c4 = i % 24;
    float4 acc = make_float4(0.f,0.f,0.f,0.f);
    #pragma unroll
    for (int z = 0; z < 16; z++)
        acc = f4add(acc, ((const float4*)parts)[(size_t)z*(M_*128/4) + (size_t)m*32 + c4]);
    if (c4 < 16) cvt_store4(acc, dtr, (size_t)m*16 + c4);
    else         ((float4*)bc)[(size_t)m*8 + (c4 - 16)] = acc;
}

// ---------------- fused build_h (8-way partial reduce) + rmsnorm (layer 0) ----------------
__global__ void build_rms_kernel(const float* __restrict__ pp2,
                                 const float* __restrict__ x,
                                 const float* __restrict__ w,
                                 float* __restrict__ h,
                                 __nv_bfloat16* __restrict__ oh) {
    int row = blockIdx.x;
    int b = row / T_;
    int t = row % T_;
    int tid = threadIdx.x;
    float4 x4;
    if (t < P_) {
        x4 = make_float4(0.f,0.f,0.f,0.f);
        size_t o = (size_t)(b*P_ + t)*(D_/4) + tid;
        #pragma unroll
        for (int z = 0; z < 8; z++)
            x4 = f4add(x4, ((const float4*)pp2)[(size_t)z*(128*D_/4) + o]);
    } else {
        x4 = ((const float4*)(x + (size_t)(b*S_ + (t - P_))*D_))[tid];
    }
    ((float4*)(h + (size_t)row*D_))[tid] = x4;
    float s = x4.x*x4.x + x4.y*x4.y + x4.z*x4.z + x4.w*x4.w;
    #pragma unroll
    for (int o = 16; o; o >>= 1) s += __shfl_xor_sync(0xffffffffu, s, o);
    __shared__ float ws[8];
    __shared__ float scale_s;
    if ((tid & 31) == 0) ws[tid >> 5] = s;
    __syncthreads();
    if (tid == 0) {
        float tt = 0.f;
        #pragma unroll
        for (int i = 0; i < 8; i++) tt += ws[i];
        scale_s = rsqrtf(tt / (float)D_ + 1e-5f);
    }
    __syncthreads();
    float sc = scale_s;
    float4 wv = ((const float4*)w)[tid];
    float4 v = make_float4(x4.x*sc*wv.x, x4.y*sc*wv.y, x4.z*sc*wv.z, x4.w*sc*wv.w);
    cvt_store4(v, oh, (size_t)row*(D_/4) + tid);
}

// rmsnorm with fused out_proj 2-partial accumulate; writes back h
__global__ void rmsnorm_acc_kernel(float* __restrict__ h,
                                   const float* __restrict__ parts,
                                   const float* __restrict__ w,
                                   __nv_bfloat16* __restrict__ oh) {
    int row = blockIdx.x;
    int tid = threadIdx.x;
    size_t o = (size_t)row*(D_/4) + tid;
    float4 x4 = ((const float4*)h)[o];
    x4 = f4add(x4, ((const float4*)parts)[o]);
    x4 = f4add(x4, ((const float4*)parts)[(size_t)(M_*D_/4) + o]);
    ((float4*)h)[o] = x4;
    float s = x4.x*x4.x + x4.y*x4.y + x4.z*x4.z + x4.w*x4.w;
    #pragma unroll
    for (int q = 16; q; q >>= 1) s += __shfl_xor_sync(0xffffffffu, s, q);
    __shared__ float ws[8];
    __shared__ float scale_s;
    if ((tid & 31) == 0) ws[tid >> 5] = s;
    __syncthreads();
    if (tid == 0) {
        float t = 0.f;
        #pragma unroll
        for (int i = 0; i < 8; i++) t += ws[i];
        scale_s = rsqrtf(t / (float)D_ + 1e-5f);
    }
    __syncthreads();
    float sc = scale_s;
    float4 wv = ((const float4*)w)[tid];
    float4 v = make_float4(x4.x*sc*wv.x, x4.y*sc*wv.y, x4.z*sc*wv.z, x4.w*sc*wv.w);
    cvt_store4(v, oh, o);
}

// final rmsnorm with fused out_proj 2-partial accumulate
__global__ void final_acc_kernel(const float* __restrict__ h,
                                 const float* __restrict__ parts,
                                 const float* __restrict__ w,
                                 float* __restrict__ out) {
    int row = blockIdx.x;
    int b = row >> 9;
    int t = row & 511;
    int hrow = b*T_ + P_ + t;
    int tid = threadIdx.x;
    size_t o = (size_t)hrow*(D_/4) + tid;
    float4 x4 = ((const float4*)h)[o];
    x4 = f4add(x4, ((const float4*)parts)[o]);
    x4 = f4add(x4, ((const float4*)parts)[(size_t)(M_*D_/4) + o]);
    float s = x4.x*x4.x + x4.y*x4.y + x4.z*x4.z + x4.w*x4.w;
    #pragma unroll
    for (int q = 16; q; q >>= 1) s += __shfl_xor_sync(0xffffffffu, s, q);
    __shared__ float ws[8];
    __shared__ float scale_s;
    if ((tid & 31) == 0) ws[tid >> 5] = s;
    __syncthreads();
    if (tid == 0) {
        float tt = 0.f;
        #pragma unroll
        for (int i = 0; i < 8; i++) tt += ws[i];
        scale_s = rsqrtf(tt / (float)D_ + 1e-5f);
    }
    __syncthreads();
    float sc = scale_s;
    float4 wv = ((const float4*)w)[tid];
    float4 o4 = make_float4(x4.x*sc*wv.x, x4.y*sc*wv.y, x4.z*sc*wv.z, x4.w*sc*wv.w);
    ((float4*)(out + (size_t)row*D_))[tid] = o4;
}

// depthwise causal conv (DC=4) + silu; reads bf16 xz, writes bf16 xi
__global__ void conv_silu4(const __nv_bfloat16* __restrict__ xzh,
                           const float* __restrict__ cw,
                           const float* __restrict__ cb,
                           __nv_bfloat16* __restrict__ xih) {
    int idx = blockIdx.x * blockDim.x + threadIdx.x;
    if (idx >= M_*(DI_/4)) return;

    int e4 = idx % (DI_/4);
    int m  = idx / (DI_/4);
    int t  = m % T_;
    float4 w0 = ((const float4*)cw)[e4*4+0];
    float4 w1 = ((const float4*)cw)[e4*4+1];
    float4 w2 = ((const float4*)cw)[e4*4+2];
    float4 w3 = ((const float4*)cw)[e4*4+3];
    float4 acc = ((const float4*)cb)[e4];
    const float* wj[4] = { (const float*)&w0, (const float*)&w1,
                           (const float*)&w2, (const float*)&w3 };
    #pragma unroll
    for (int j = 0; j < 4; j++) {
        int tt = t - 3 + j;
        if (tt >= 0) {
            uint2 raw = *(const uint2*)(xzh + (size_t)(m - 3 + j)*(2*DI_) + e4*4);
            __nv_bfloat162 p0 = *(__nv_bfloat162*)&raw.x;
            __nv_bfloat162 p1 = *(__nv_bfloat162*)&raw.y;
            acc.x = fmaf(bf2f(p0.x), wj[0][j], acc.x);
            acc.y = fmaf(bf2f(p0.y), wj[1][j], acc.y);
            acc.z = fmaf(bf2f(p1.x), wj[2][j], acc.z);
            acc.w = fmaf(bf2f(p1.y), wj[3][j], acc.w);
        }
    }
    float4 v = make_float4(siluf(acc.x), siluf(acc.y), siluf(acc.z), siluf(acc.w));
    cvt_store4(v, xih, idx);
}

// ---------------- selective scan, double-buffered cp.async staging ----------------
// block = 256 threads (8 warps), 16 channels; warp w computes channels 2w, 2w+1.
__global__ void __launch_bounds__(256)
scan_kernel(const __nv_bfloat16* __restrict__ xzh,
            const __nv_bfloat16* __restrict__ xih,
            const float* __restrict__ bc,
            const float* __restrict__ dt,
            const float* __restrict__ A_log,
            const float* __restrict__ Dp,
            __nv_bfloat16* __restrict__ yh) {
    __shared__ __align__(16) float sdt[2][16][16], sB[2][16][16], sC[2][16][16];
    __shared__ __align__(16) __nv_bfloat16 sxi[2][16][16], sz[2][16][16];
    __shared__ uint32_t sy[16][8];

    const int tid  = threadIdx.x;
    const int lane = tid & 31;
    const int warp = tid >> 5;
    const int blk  = blockIdx.x;
    const int b    = blk >> 7;
    const int e0   = (blk & 127) * 16;
    const int m0   = b * T_;

    const int cloc = 2 * warp + (lane >> 4);
    const int s    = lane & 15;
    const int e    = e0 + cloc;

    const float A  = -expf(A_log[(size_t)e*DS_ + s]);
    const float Dv = Dp[e];
    float h = 0.f;

    auto load_chunk = [&](int buf, int tb) {
        if (tid < 64) {
            int r = tid >> 2, c = tid & 3;
            cp16(smem_u32(&sdt[buf][r][c*4]), dt + (size_t)(m0 + tb + r)*DI_ + e0 + c*4);
        } else if (tid < 128) {
            int t2 = tid - 64;
            int r = t2 >> 2, c = t2 & 3;
            cp16(smem_u32(&sB[buf][r][c*4]), bc + (size_t)(m0 + tb + r)*32 + c*4);
        } else if (tid < 192) {
            int t2 = tid - 128;
            int r = t2 >> 2, c = t2 & 3;
            cp16(smem_u32(&sC[buf][r][c*4]), bc + (size_t)(m0 + tb + r)*32 + 16 + c*4);
        } else if (tid < 224) {
            int t2 = tid - 192;
            int r = t2 >> 1, c = t2 & 1;
            cp16(smem_u32(&sxi[buf][r][c*8]), xih + (size_t)(m0 + tb + r)*DI_ + e0 + c*8);
        } else {
            int t2 = tid - 224;
            int r = t2 >> 1, c = t2 & 1;
            cp16(smem_u32(&sz[buf][r][c*8]), xzh + (size_t)(m0 + tb + r)*(2*DI_) + DI_ + e0 + c*8);
        }
    };

    load_chunk(0, 0);
    cp_commit();

    for (int ci = 0; ci < T_/16; ci++) {
        if (ci + 1 < T_/16) load_chunk((ci + 1) & 1, (ci + 1) * 16);
        cp_commit();
        cp_wait<1>();
        __syncthreads();

        const int buf = ci & 1;
        float p[16];
        #pragma unroll
        for (int j = 0; j < 16; j++) {
            float dtv = sdt[buf][j][cloc];
            float dA  = __expf(dtv * A);
            h = fmaf(dA, h, dtv * sB[buf][j][s] * bf2f(sxi[buf][j][cloc]));
            p[j] = h * sC[buf][j][s];
        }
        #pragma unroll
        for (int o = 8; o >= 1; o >>= 1)
            #pragma unroll
            for (int j = 0; j < 16; j++)
                p[j] += __shfl_xor_sync(0xffffffffu, p[j], o);
        #pragma unroll
        for (int j = 0; j < 16; j++) {
            float val = (p[j] + bf2f(sxi[buf][j][cloc]) * Dv) * siluf(bf2f(sz[buf][j][cloc]));
            float v1  = __shfl_down_sync(0xffffffffu, val, 16);
            if (lane == 0) sy[j][warp] = pack2(val, v1);
        }
        __syncthreads();   // compute reads of buf done; sy writes done

        if (tid < 128) {
            int t = tid >> 3, q = tid & 7;
            ((uint32_t*)yh)[((size_t)(m0 + ci*16 + t)*DI_ + e0) / 2 + q] = sy[t][q];
        }
        // NOTE: no trailing __syncthreads needed — next iteration's top-of-loop
        // barrier orders these sy reads against the next compute-phase writes,
        // and this barrier (above) already ordered buffer reuse for the loads.
    }
}

// ---------------- host orchestration ----------------
extern "C" void kernel_launch(void* const* d_in, const int* in_sizes, int n_in,
                              void* d_out, int out_size) {
    (void)in_sizes; (void)n_in; (void)out_size;
    const float* x      = (const float*)d_in[0];
    const float* pc     = (const float*)d_in[1];
    const float* w1     = (const float*)d_in[2];
    const float* w2     = (const float*)d_in[3];
    const float* norm_w = (const float*)d_in[4];
    const float* ipw    = (const float*)d_in[5];
    const float* cw     = (const float*)d_in[6];
    const float* cb     = (const float*)d_in[7];
    const float* xpw    = (const float*)d_in[8];
    const float* dtw    = (const float*)d_in[9];
    const float* dtb    = (const float*)d_in[10];
    const float* A_log  = (const float*)d_in[11];
    const float* Dparam = (const float*)d_in[12];
    const float* opw    = (const float*)d_in[13];
    const float* fnw    = (const float*)d_in[14];

    float *h, *dtp, *bcp, *part16, *part2, *pp1, *pp2;
    cudaGetSymbolAddress((void**)&h,      g_h);
    cudaGetSymbolAddress((void**)&dtp,    g_dt);
    cudaGetSymbolAddress((void**)&bcp,    g_bc);
    cudaGetSymbolAddress((void**)&part16, g_part16);
    cudaGetSymbolAddress((void**)&part2,  g_part2);
    cudaGetSymbolAddress((void**)&pp1,    g_pp1);
    cudaGetSymbolAddress((void**)&pp2,    g_pp2);

    __nv_bfloat16 *xzh, *xnh, *xih, *yh, *dtrh, *ipwh, *opwh, *xpwh, *dtwh, *pch, *p1h, *w1t, *w2t;
    cudaGetSymbolAddress((void**)&xzh,  g_xz_h);
    cudaGetSymbolAddress((void**)&xnh,  g_xn_h);
    cudaGetSymbolAddress((void**)&xih,  g_xi_h);
    cudaGetSymbolAddress((void**)&yh,   g_y_h);
    cudaGetSymbolAddress((void**)&dtrh, g_dtr_h);
    cudaGetSymbolAddress((void**)&ipwh, g_ipw_h);
    cudaGetSymbolAddress((void**)&opwh, g_opw_h);
    cudaGetSymbolAddress((void**)&xpwh, g_xpw_h);
    cudaGetSymbolAddress((void**)&dtwh, g_dtw_h);
    cudaGetSymbolAddress((void**)&pch,  g_pc_h);
    cudaGetSymbolAddress((void**)&p1h,  g_p1_h);
    cudaGetSymbolAddress((void**)&w1t,  g_w1t);
    cudaGetSymbolAddress((void**)&w2t,  g_w2t);

    cudaFuncSetAttribute(tc_gemm<3>, cudaFuncAttributeMaxDynamicSharedMemorySize, GEMM_DYN);
    cudaFuncSetAttribute(tc_gemm<4>, cudaFuncAttributeMaxDynamicSharedMemorySize, GEMM_DYN);

    // ---- converts + transposes (1 launch) ----
    convert_all<<<CW_BLK + TP_W1 + TP_W2, 256>>>(ipw, ipwh, opw, opwh, dtw, dtwh,
                                                 xpw, xpwh, pc, pch, w1, w1t, w2, w2t);

    // ---- prepend MLP, split-K partials (no atomics) ----
    tc_gemm<4><<<dim3(1, 8, 6), 256, GEMM_DYN>>>(pch, w1t, pp1, PCD_, D_, (size_t)128*D_);
    silu_cvt_red<<<(128*D_/4+255)/256, 256>>>(pp1, p1h);
    tc_gemm<4><<<dim3(1, 8, 8), 256, GEMM_DYN>>>(p1h, w2t, pp2, D_, D_, (size_t)128*D_);
    build_rms_kernel<<<M_, 256>>>(pp2, x, norm_w, h, xnh);

    // ---- 4 mamba layers ----
    for (int l = 0; l < L_; l++) {
        // xz = xn @ in_proj_w^T -> bf16  (288 CTAs)
        tc_gemm<3><<<dim3(9, 32, 1), 256, GEMM_DYN>>>(
            xnh, ipwh + (size_t)l*2*DI_*D_, xzh, D_, 2*DI_, 0);

        conv_silu4<<<(M_*(DI_/4)+255)/256, 256>>>(
            xzh, cw + (size_t)l*DI_*4, cb + (size_t)l*DI_, xih);

        // x_proj partials (144 CTAs, split-K=16)
        tc_gemm<4><<<dim3(9, 1, 16), 256, GEMM_DYN>>>(
            xih, xpwh + (size_t)l*128*DI_, part16, DI_, 128, (size_t)M_*128);
        reduce_xdbl<<<(M_*24+255)/256, 256>>>(part16, dtrh, bcp);

        // dt = softplus(dtr @ dt_proj_w^T + b)
        dtproj_kernel<<<dim3(9, 16), 256>>>(
            dtrh, dtwh + (size_t)l*DI_*DR_, dtb + (size_t)l*DI_, dtp);

        // selective scan + gate -> y bf16 (double-buffered staging, 256 CTAs)
        scan_kernel<<<B_*(DI_/16), 256>>>(
            xzh, xih, bcp, dtp,
            A_log + (size_t)l*DI_*DS_, Dparam + (size_t)l*DI_, yh);

        // out_proj partials (144 CTAs, split-K=2)
        tc_gemm<4><<<dim3(9, 8, 2), 256, GEMM_DYN>>>(
            yh, opwh + (size_t)l*D_*DI_, part2, DI_, D_, (size_t)M_*D_);

        if (l < L_ - 1)
            rmsnorm_acc_kernel<<<M_, 256>>>(h, part2, norm_w + (size_t)(l+1)*D_, xnh);
        else
            final_acc_kernel<<<B_*S_, 256>>>(h, part2, fnw, (float*)d_out);
    }
}